// round 3
// baseline (speedup 1.0000x reference)
#include <cuda_runtime.h>
#include <cuda_bf16.h>
#include <cstdint>
#include <math.h>

#define NB 8
#define CC 256
#define NPIX 1024
#define HEADS 8
#define HD 128
#define MQKV 3072
#define DIM 1024

// Hamilton tables
__constant__ int   c_IDX[16] = {0,1,2,3, 1,0,3,2, 2,3,0,1, 3,2,1,0};
__constant__ float c_SGN[16] = {1.f,-1.f,-1.f,-1.f, 1.f,1.f,1.f,-1.f,
                                1.f,-1.f,1.f,1.f, 1.f,1.f,-1.f,1.f};

// Scratch (device globals; no runtime allocation allowed)
__device__ __nv_bfloat16 g_WeffH[(size_t)MQKV*DIM];
__device__ __nv_bfloat16 g_WeffL[(size_t)MQKV*DIM];
__device__ __nv_bfloat16 g_WprojH[(size_t)DIM*DIM];
__device__ __nv_bfloat16 g_WprojL[(size_t)DIM*DIM];
__device__ __nv_bfloat16 g_XTH[(size_t)NB*NPIX*DIM];   // (b, n, k) bf16 hi
__device__ __nv_bfloat16 g_XTL[(size_t)NB*NPIX*DIM];   // (b, n, k) bf16 lo
__device__ float g_Q[(size_t)NB*HEADS*HD*NPIX];        // (B,H,d,N), pre-scaled
__device__ float g_K[(size_t)NB*HEADS*HD*NPIX];
__device__ float g_V[(size_t)NB*HEADS*HD*NPIX];
__device__ __nv_bfloat16 g_OTH[(size_t)NB*NPIX*DIM];   // attention out (b,n,ch) hi
__device__ __nv_bfloat16 g_OTL[(size_t)NB*NPIX*DIM];   // attention out (b,n,ch) lo

// ===========================================================================
// Helpers (base-ISA only: cp.async / ldmatrix / mma.sync)
// ===========================================================================
__device__ __forceinline__ uint32_t smem_u32(const void* p){
  uint32_t a;
  asm("{ .reg .u64 t; cvta.to.shared.u64 t, %1; cvt.u32.u64 %0, t; }"
      : "=r"(a) : "l"(p));
  return a;
}
__device__ __forceinline__ void cpasync16(uint32_t s, const void* g){
  asm volatile("cp.async.cg.shared.global [%0], [%1], 16;" :: "r"(s), "l"(g));
}
__device__ __forceinline__ void ldm4(uint32_t r[4], uint32_t addr){
  asm volatile("ldmatrix.sync.aligned.m8n8.x4.shared.b16 {%0,%1,%2,%3}, [%4];"
    : "=r"(r[0]),"=r"(r[1]),"=r"(r[2]),"=r"(r[3]) : "r"(addr));
}
__device__ __forceinline__ void mma16816(float c[4], const uint32_t a[4],
                                         const uint32_t b[2]){
  asm volatile(
    "mma.sync.aligned.m16n8k16.row.col.f32.bf16.bf16.f32 "
    "{%0,%1,%2,%3}, {%4,%5,%6,%7}, {%8,%9}, {%0,%1,%2,%3};"
    : "+f"(c[0]),"+f"(c[1]),"+f"(c[2]),"+f"(c[3])
    : "r"(a[0]),"r"(a[1]),"r"(a[2]),"r"(a[3]), "r"(b[0]),"r"(b[1]));
}

// ===========================================================================
// Prep: Hamilton-folded weights -> bf16 hi/lo
// ===========================================================================
__global__ void prep_weff_kernel(const float* __restrict__ w_qkv){
  int idx = blockIdx.x*256 + threadIdx.x;
  int g = idx >> 10, k = idx & 1023;
  int qc = g / 768, o = g - qc*768;
  int p = k >> 8, cch = k & 255;
  float w = c_SGN[qc*4+p] * w_qkv[(c_IDX[qc*4+p]*768 + o)*256 + cch];
  __nv_bfloat16 h = __float2bfloat16(w);
  g_WeffH[idx] = h;
  g_WeffL[idx] = __float2bfloat16(w - __bfloat162float(h));
}

__global__ void prep_wproj_kernel(const float* __restrict__ w_proj){
  int idx = blockIdx.x*256 + threadIdx.x;
  int g = idx >> 10, k = idx & 1023;
  int qc = g >> 8, o = g & 255;
  int p = k >> 8, cch = k & 255;
  float w = c_SGN[qc*4+p] * w_proj[(c_IDX[qc*4+p]*256 + o)*256 + cch];
  __nv_bfloat16 h = __float2bfloat16(w);
  g_WprojH[idx] = h;
  g_WprojL[idx] = __float2bfloat16(w - __bfloat162float(h));
}

// x (b, cch, p, n) fp32 -> XT (b, n, k=p*256+cch) bf16 hi/lo   (32x32 tiles)
__global__ void prep_xt_kernel(const float* __restrict__ x){
  __shared__ float sm[32][33];
  int b = blockIdx.z, k0 = blockIdx.x*32, n0 = blockIdx.y*32;
  int t = threadIdx.x;
  {
    int kk = t >> 3, n4 = (t & 7) << 2;
    int k = k0 + kk; int p = k >> 8, cch = k & 255;
    float4 v = *(const float4*)&x[((size_t)((b*CC+cch)*4 + p))*NPIX + n0 + n4];
    sm[kk][n4] = v.x; sm[kk][n4+1] = v.y; sm[kk][n4+2] = v.z; sm[kk][n4+3] = v.w;
  }
  __syncthreads();
  {
    int nn = t >> 3, k4 = (t & 7) << 2;
    float a0 = sm[k4+0][nn], a1 = sm[k4+1][nn], a2 = sm[k4+2][nn], a3 = sm[k4+3][nn];
    __nv_bfloat16 h0 = __float2bfloat16(a0), h1 = __float2bfloat16(a1);
    __nv_bfloat16 h2 = __float2bfloat16(a2), h3 = __float2bfloat16(a3);
    __nv_bfloat16 l0 = __float2bfloat16(a0 - __bfloat162float(h0));
    __nv_bfloat16 l1 = __float2bfloat16(a1 - __bfloat162float(h1));
    __nv_bfloat16 l2 = __float2bfloat16(a2 - __bfloat162float(h2));
    __nv_bfloat16 l3 = __float2bfloat16(a3 - __bfloat162float(h3));
    size_t o = ((size_t)(b*NPIX) + n0 + nn)*DIM + k0 + k4;
    uint2 hp = make_uint2((uint32_t)__bfloat16_as_ushort(h0) | ((uint32_t)__bfloat16_as_ushort(h1)<<16),
                          (uint32_t)__bfloat16_as_ushort(h2) | ((uint32_t)__bfloat16_as_ushort(h3)<<16));
    uint2 lp = make_uint2((uint32_t)__bfloat16_as_ushort(l0) | ((uint32_t)__bfloat16_as_ushort(l1)<<16),
                          (uint32_t)__bfloat16_as_ushort(l2) | ((uint32_t)__bfloat16_as_ushort(l3)<<16));
    *(uint2*)&g_XTH[o] = hp;
    *(uint2*)&g_XTL[o] = lp;
  }
}

// ===========================================================================
// mma.sync GEMM: C(128m x 128n) per CTA, K=1024, bf16x3 split.
// A row-major (m,k), B "col-major" stored (n,k); both K-major in gmem.
// BK=32, 2-stage cp.async double buffer, smem rows padded to 80B.
// MODE 0: A=Weff (M=3072), B=XT  -> scatter Q/K/V (+bias, Q pre-scaled)
// MODE 1: A=Wproj (M=1024), B=OT -> final output (+bias)
// ===========================================================================
#define AROWB 80                 // bytes per smem row (64 data + 16 pad)
#define TILE_B (128*AROWB)       // 10240 bytes per (array) tile
#define STAGE_B (4*TILE_B)       // Ah, Al, Bh, Bl
#define GEMM_SMEM (2*STAGE_B)    // 81920

template<int MODE>
__global__ __launch_bounds__(256, 1) void gemm_mma(const float* __restrict__ bias,
                                                   float* __restrict__ outp){
  extern __shared__ char smem[];
  const uint32_t sb = smem_u32(smem);

  const int tid = threadIdx.x;
  const int wid = tid >> 5, lane = tid & 31;
  const int m0 = blockIdx.x * 128;
  const int b  = blockIdx.y >> 3;
  const int n0 = (blockIdx.y & 7) << 7;
  const int wm = (wid >> 2) * 64;
  const int wn = (wid & 3) * 32;

  const __nv_bfloat16* Agh = (MODE==0 ? g_WeffH : g_WprojH) + (size_t)m0*DIM;
  const __nv_bfloat16* Agl = (MODE==0 ? g_WeffL : g_WprojL) + (size_t)m0*DIM;
  const __nv_bfloat16* Bgh = (MODE==0 ? g_XTH : g_OTH) + ((size_t)(b*NPIX) + n0)*DIM;
  const __nv_bfloat16* Bgl = (MODE==0 ? g_XTL : g_OTL) + ((size_t)(b*NPIX) + n0)*DIM;

  float acc[4][4][4];
  #pragma unroll
  for (int i=0;i<4;i++)
    #pragma unroll
    for (int j=0;j<4;j++)
      #pragma unroll
      for (int r=0;r<4;r++) acc[i][j][r] = 0.f;

  // loader: 512 x 16B per array per stage; thread does 2 ops per array
  auto issue = [&](int kt, int buf){
    const uint32_t sbuf = sb + buf*STAGE_B;
    #pragma unroll
    for (int i=0;i<2;i++){
      int o = tid + i*256;
      int row = o >> 2, c16 = o & 3;
      size_t goff = (size_t)row*DIM + kt*32 + c16*8;   // bf16 elements
      uint32_t soff = row*AROWB + c16*16;
      cpasync16(sbuf + soff,            Agh + goff);
      cpasync16(sbuf + TILE_B + soff,   Agl + goff);
      cpasync16(sbuf + 2*TILE_B + soff, Bgh + goff);
      cpasync16(sbuf + 3*TILE_B + soff, Bgl + goff);
    }
  };

  issue(0, 0);
  asm volatile("cp.async.commit_group;" ::: "memory");

  for (int kt = 0; kt < 32; kt++){
    if (kt + 1 < 32){
      issue(kt+1, (kt+1)&1);
      asm volatile("cp.async.commit_group;" ::: "memory");
      asm volatile("cp.async.wait_group 1;" ::: "memory");
    } else {
      asm volatile("cp.async.wait_group 0;" ::: "memory");
    }
    __syncthreads();

    const uint32_t Ah = sb + (kt&1)*STAGE_B;
    const uint32_t Al = Ah + TILE_B;
    const uint32_t Bh = Ah + 2*TILE_B;
    const uint32_t Bl = Ah + 3*TILE_B;

    #pragma unroll
    for (int ks = 0; ks < 2; ks++){
      uint32_t ah[4][4], al[4][4], bh[4][2], bl[4][2];
      #pragma unroll
      for (int mi = 0; mi < 4; mi++){
        uint32_t off = (uint32_t)(wm + mi*16 + (lane & 15))*AROWB
                     + ks*32 + (lane >> 4)*16;
        ldm4(ah[mi], Ah + off);
        ldm4(al[mi], Al + off);
      }
      #pragma unroll
      for (int np = 0; np < 2; np++){
        uint32_t off = (uint32_t)(wn + np*16 + (lane >> 4)*8 + (lane & 7))*AROWB
                     + ks*32 + ((lane >> 3) & 1)*16;
        uint32_t r[4];
        ldm4(r, Bh + off);
        bh[np*2][0]=r[0]; bh[np*2][1]=r[1]; bh[np*2+1][0]=r[2]; bh[np*2+1][1]=r[3];
        ldm4(r, Bl + off);
        bl[np*2][0]=r[0]; bl[np*2][1]=r[1]; bl[np*2+1][0]=r[2]; bl[np*2+1][1]=r[3];
      }
      #pragma unroll
      for (int mi=0;mi<4;mi++)
        #pragma unroll
        for (int ni=0;ni<4;ni++) mma16816(acc[mi][ni], ah[mi], bh[ni]);
      #pragma unroll
      for (int mi=0;mi<4;mi++)
        #pragma unroll
        for (int ni=0;ni<4;ni++) mma16816(acc[mi][ni], ah[mi], bl[ni]);
      #pragma unroll
      for (int mi=0;mi<4;mi++)
        #pragma unroll
        for (int ni=0;ni<4;ni++) mma16816(acc[mi][ni], al[mi], bh[ni]);
    }
    __syncthreads();
  }

  // ---- epilogue: direct stores from fragments ----
  const float qscale = 0.08838834764831845f;
  #pragma unroll
  for (int mi=0;mi<4;mi++)
    #pragma unroll
    for (int half=0; half<2; half++){
      int gm = m0 + wm + mi*16 + (lane >> 2) + half*8;
      float bi = bias[gm];
      if (MODE==0){
        int qc = gm / 768; int o = gm - qc*768; int s3 = o >> 8; int cch = o & 255;
        int ch = (qc << 8) | cch; int hh = ch >> 7; int dd = ch & 127;
        float sc = (s3 == 0) ? qscale : 1.f;
        float* dst = (s3 == 0 ? g_Q : (s3 == 1 ? g_K : g_V))
                   + ((size_t)((b*HEADS + hh)*HD + dd))*NPIX;
        #pragma unroll
        for (int ni=0;ni<4;ni++){
          int nn = n0 + wn + ni*8 + (lane & 3)*2;
          float2 v = make_float2((acc[mi][ni][half*2+0] + bi)*sc,
                                 (acc[mi][ni][half*2+1] + bi)*sc);
          *(float2*)&dst[nn] = v;
        }
      } else {
        int qc = gm >> 8; int cch = gm & 255;
        float* dst = outp + ((size_t)((b*CC + cch)*4 + qc))*NPIX;
        #pragma unroll
        for (int ni=0;ni<4;ni++){
          int nn = n0 + wn + ni*8 + (lane & 3)*2;
          float2 v = make_float2(acc[mi][ni][half*2+0] + bi,
                                 acc[mi][ni][half*2+1] + bi);
          *(float2*)&dst[nn] = v;
        }
      }
    }
}

// ---------------------------------------------------------------------------
// Flash attention, fp32. One CTA = one (b,h) x 64-query block. 256 threads.
// Q,K,V in (B,H,d=128,N=1024); Q pre-scaled. Writes O as bf16 hi/lo (b,n,ch).
// ---------------------------------------------------------------------------
#define ATT_SMEM_FLOATS (8192 + 8192 + 64*133 + 64*68 + 64*3 + 256)

__global__ __launch_bounds__(256) void attn_kernel(){
  extern __shared__ float sm[];
  float* Qs  = sm;                 // [128][64]
  float* Ks  = Qs  + 8192;         // [128][64]
  float* Vts = Ks  + 8192;         // [64][133]
  float* Ps  = Vts + 64*133;       // [64][68]
  float* s_m = Ps  + 64*68;
  float* s_l = s_m + 64;
  float* s_al= s_l + 64;
  float* red = s_al+ 64;

  const int tid = threadIdx.x;
  const int bh  = blockIdx.y;
  const int n0  = blockIdx.x * 64;
  const float* qbase = g_Q + (size_t)bh * HD * NPIX;
  const float* kbase = g_K + (size_t)bh * HD * NPIX;
  const float* vbase = g_V + (size_t)bh * HD * NPIX;

  const int lr = tid >> 4;
  const int lc = tid & 15;

  #pragma unroll
  for (int rep = 0; rep < 8; rep++){
    int d = rep*16 + lr;
    float4 v = *(const float4*)&qbase[(size_t)d*NPIX + n0 + lc*4];
    *(float4*)&Qs[d*64 + lc*4] = v;
  }
  if (tid < 64){ s_m[tid] = -1e30f; s_l[tid] = 0.f; }

  float accO[4][8];
  #pragma unroll
  for (int i=0;i<4;i++)
    #pragma unroll
    for (int j=0;j<8;j++) accO[i][j] = 0.f;

  const int row  = tid >> 2;
  const int part = tid & 3;

  for (int mt = 0; mt < 16; mt++){
    const int m0 = mt*64;
    __syncthreads();
    #pragma unroll
    for (int rep = 0; rep < 8; rep++){
      int d = rep*16 + lr;
      float4 kv = *(const float4*)&kbase[(size_t)d*NPIX + m0 + lc*4];
      *(float4*)&Ks[d*64 + lc*4] = kv;
      float4 vv = *(const float4*)&vbase[(size_t)d*NPIX + m0 + lc*4];
      Vts[(lc*4+0)*133 + d] = vv.x;
      Vts[(lc*4+1)*133 + d] = vv.y;
      Vts[(lc*4+2)*133 + d] = vv.z;
      Vts[(lc*4+3)*133 + d] = vv.w;
    }
    __syncthreads();

    float accS[4][4];
    #pragma unroll
    for (int i=0;i<4;i++)
      #pragma unroll
      for (int j=0;j<4;j++) accS[i][j] = 0.f;
    #pragma unroll 4
    for (int d = 0; d < 128; d++){
      float4 qv = *(const float4*)&Qs[d*64 + lr*4];
      float4 kv = *(const float4*)&Ks[d*64 + lc*4];
      float qa[4] = {qv.x,qv.y,qv.z,qv.w};
      float ka[4] = {kv.x,kv.y,kv.z,kv.w};
      #pragma unroll
      for (int i=0;i<4;i++)
        #pragma unroll
        for (int j=0;j<4;j++) accS[i][j] = fmaf(qa[i], ka[j], accS[i][j]);
    }
    #pragma unroll
    for (int i=0;i<4;i++)
      *(float4*)&Ps[(lr*4+i)*68 + lc*4] =
        make_float4(accS[i][0],accS[i][1],accS[i][2],accS[i][3]);
    __syncthreads();

    float mx = -1e30f;
    #pragma unroll
    for (int m=0;m<16;m++) mx = fmaxf(mx, Ps[row*68 + part*16 + m]);
    red[tid] = mx;
    __syncthreads();
    if (tid < 64){
      float mnew = fmaxf(fmaxf(red[tid*4],red[tid*4+1]), fmaxf(red[tid*4+2],red[tid*4+3]));
      mnew = fmaxf(mnew, s_m[tid]);
      s_al[tid] = __expf(s_m[tid] - mnew);
      s_m[tid] = mnew;
    }
    __syncthreads();
    float mnew = s_m[row];
    float lsum = 0.f;
    #pragma unroll
    for (int m=0;m<16;m++){
      float e = __expf(Ps[row*68 + part*16 + m] - mnew);
      Ps[row*68 + part*16 + m] = e;
      lsum += e;
    }
    red[tid] = lsum;
    __syncthreads();
    if (tid < 64)
      s_l[tid] = s_l[tid]*s_al[tid] + (red[tid*4]+red[tid*4+1]+red[tid*4+2]+red[tid*4+3]);

    #pragma unroll
    for (int i=0;i<4;i++){
      float a = s_al[lr*4+i];
      #pragma unroll
      for (int j=0;j<8;j++) accO[i][j] *= a;
    }
    for (int m4 = 0; m4 < 64; m4 += 4){
      float pv[4][4];
      #pragma unroll
      for (int i=0;i<4;i++){
        float4 t = *(const float4*)&Ps[(lr*4+i)*68 + m4];
        pv[i][0]=t.x; pv[i][1]=t.y; pv[i][2]=t.z; pv[i][3]=t.w;
      }
      #pragma unroll
      for (int mi=0; mi<4; mi++){
        float vv[8];
        #pragma unroll
        for (int j=0;j<8;j++) vv[j] = Vts[(m4+mi)*133 + lc + 16*j];
        #pragma unroll
        for (int i=0;i<4;i++)
          #pragma unroll
          for (int j=0;j<8;j++) accO[i][j] = fmaf(pv[i][mi], vv[j], accO[i][j]);
      }
    }
  }
  __syncthreads();

  // Write O as bf16 hi/lo, transposed (b, n, ch) for the proj GEMM B operand
  const int h = bh & 7, b = bh >> 3;
  #pragma unroll
  for (int i=0;i<4;i++){
    int n = n0 + lr*4 + i;
    float inv = 1.f / s_l[lr*4+i];
    #pragma unroll
    for (int j=0;j<8;j++){
      int d = lc + 16*j;
      float v = accO[i][j]*inv;
      __nv_bfloat16 hi = __float2bfloat16(v);
      size_t o = ((size_t)(b*NPIX) + n)*DIM + h*HD + d;
      g_OTH[o] = hi;
      g_OTL[o] = __float2bfloat16(v - __bfloat162float(hi));
    }
  }
}

// ---------------------------------------------------------------------------
// Quaternion depthwise 3x3, accumulates into final output.
// ---------------------------------------------------------------------------
__global__ __launch_bounds__(256) void qdwconv_kernel(const float* __restrict__ x,
                                                      const float* __restrict__ w_pe,
                                                      const float* __restrict__ b_pe,
                                                      float* __restrict__ outp){
  __shared__ float xs[4][1024];
  __shared__ float wt[4][4][9];
  const int bid = blockIdx.x;
  const int c = bid & 255, b = bid >> 8;
  const int tid = threadIdx.x;

  #pragma unroll
  for (int p=0;p<4;p++){
    const float* xp = x + ((size_t)((b*CC + c)*4 + p))*NPIX;
    for (int k=tid; k<1024; k+=256) xs[p][k] = xp[k];
  }
  if (tid < 144){
    int qc = tid/36, p = (tid/9)&3, t = tid%9;
    wt[qc][p][t] = c_SGN[qc*4+p] * w_pe[(c_IDX[qc*4+p]*CC + c)*9 + t];
  }
  __syncthreads();

  float bia[4];
  #pragma unroll
  for (int qc=0;qc<4;qc++) bia[qc] = b_pe[qc*CC + c];

  for (int k=tid; k<1024; k+=256){
    int hh = k >> 5, ww = k & 31;
    float acc[4] = {bia[0],bia[1],bia[2],bia[3]};
    #pragma unroll
    for (int p=0;p<4;p++){
      #pragma unroll
      for (int kh=0;kh<3;kh++){
        int h2 = hh + kh - 1;
        if (h2 < 0 || h2 > 31) continue;
        #pragma unroll
        for (int kw=0;kw<3;kw++){
          int w2 = ww + kw - 1;
          if (w2 < 0 || w2 > 31) continue;
          float xv = xs[p][h2*32 + w2];
          #pragma unroll
          for (int qc=0;qc<4;qc++) acc[qc] = fmaf(wt[qc][p][kh*3+kw], xv, acc[qc]);
        }
      }
    }
    #pragma unroll
    for (int qc=0;qc<4;qc++)
      outp[((size_t)((b*CC + c)*4 + qc))*NPIX + k] += acc[qc];
  }
}

// ---------------------------------------------------------------------------
extern "C" void kernel_launch(void* const* d_in, const int* in_sizes, int n_in,
                              void* d_out, int out_size){
  const float* x      = (const float*)d_in[0];
  const float* w_qkv  = (const float*)d_in[1];
  const float* b_qkv  = (const float*)d_in[2];
  const float* w_proj = (const float*)d_in[3];
  const float* b_proj = (const float*)d_in[4];
  const float* w_pe   = (const float*)d_in[5];
  const float* b_pe   = (const float*)d_in[6];
  float* outp = (float*)d_out;

  (void)in_sizes; (void)n_in; (void)out_size;

  const size_t att_smem = (size_t)ATT_SMEM_FLOATS * sizeof(float);
  cudaFuncSetAttribute(attn_kernel, cudaFuncAttributeMaxDynamicSharedMemorySize,
                       (int)att_smem);
  cudaFuncSetAttribute(gemm_mma<0>, cudaFuncAttributeMaxDynamicSharedMemorySize,
                       GEMM_SMEM);
  cudaFuncSetAttribute(gemm_mma<1>, cudaFuncAttributeMaxDynamicSharedMemorySize,
                       GEMM_SMEM);

  prep_weff_kernel <<< (MQKV*DIM)/256, 256 >>> (w_qkv);
  prep_wproj_kernel<<< (DIM*DIM)/256, 256 >>> (w_proj);
  prep_xt_kernel   <<< dim3(32,32,8), 256 >>> (x);

  // QKV: (3072 x 8192) mma.sync bf16x3
  gemm_mma<0><<< dim3(24,64), 256, GEMM_SMEM >>>(b_qkv, nullptr);

  // Attention
  attn_kernel<<< dim3(16,64), 256, att_smem >>>();

  // Proj: (1024 x 8192) mma.sync bf16x3 -> final output (+bias)
  gemm_mma<1><<< dim3(8,64), 256, GEMM_SMEM >>>(b_proj, outp);

  // Positional depthwise conv, accumulate
  qdwconv_kernel<<< NB*CC, 256 >>>(x, w_pe, b_pe, outp);
}

// round 4
// speedup vs baseline: 2.8793x; 2.8793x over previous
#include <cuda_runtime.h>
#include <cuda_bf16.h>
#include <cstdint>
#include <math.h>

#define NB 8
#define CC 256
#define NPIX 1024
#define HEADS 8
#define HD 128
#define MQKV 3072
#define DIM 1024

// Hamilton tables
__constant__ int   c_IDX[16] = {0,1,2,3, 1,0,3,2, 2,3,0,1, 3,2,1,0};
__constant__ float c_SGN[16] = {1.f,-1.f,-1.f,-1.f, 1.f,1.f,1.f,-1.f,
                                1.f,-1.f,1.f,1.f, 1.f,1.f,-1.f,1.f};

// Scratch (device globals; no runtime allocation allowed)
__device__ __nv_bfloat16 g_WeffH[(size_t)MQKV*DIM];
__device__ __nv_bfloat16 g_WeffL[(size_t)MQKV*DIM];
__device__ __nv_bfloat16 g_WprojH[(size_t)DIM*DIM];
__device__ __nv_bfloat16 g_WprojL[(size_t)DIM*DIM];
__device__ __nv_bfloat16 g_XTH[(size_t)NB*NPIX*DIM];   // (b, n, k) bf16 hi
__device__ __nv_bfloat16 g_XTL[(size_t)NB*NPIX*DIM];
__device__ float g_Q[(size_t)NB*HEADS*HD*NPIX];        // (bh, d, N) fp32 (Q pre-scaled 1/sqrt(d))
__device__ float g_K[(size_t)NB*HEADS*HD*NPIX];
__device__ float g_V[(size_t)NB*HEADS*HD*NPIX];
// attention operands, bf16 hi/lo
__device__ __nv_bfloat16 g_QTH[(size_t)NB*HEADS*NPIX*HD];  // (bh, n, d), x log2e
__device__ __nv_bfloat16 g_QTL[(size_t)NB*HEADS*NPIX*HD];
__device__ __nv_bfloat16 g_KTH[(size_t)NB*HEADS*NPIX*HD];  // (bh, n, d)
__device__ __nv_bfloat16 g_KTL[(size_t)NB*HEADS*NPIX*HD];
__device__ __nv_bfloat16 g_VH[(size_t)NB*HEADS*HD*NPIX];   // (bh, d, N)
__device__ __nv_bfloat16 g_VL[(size_t)NB*HEADS*HD*NPIX];
__device__ __nv_bfloat16 g_OTH[(size_t)NB*NPIX*DIM];   // attention out (b,n,ch) hi
__device__ __nv_bfloat16 g_OTL[(size_t)NB*NPIX*DIM];

// ===========================================================================
// Helpers (base-ISA only: cp.async / ldmatrix / mma.sync)
// ===========================================================================
__device__ __forceinline__ uint32_t smem_u32(const void* p){
  uint32_t a;
  asm("{ .reg .u64 t; cvta.to.shared.u64 t, %1; cvt.u32.u64 %0, t; }"
      : "=r"(a) : "l"(p));
  return a;
}
__device__ __forceinline__ void cpasync16(uint32_t s, const void* g){
  asm volatile("cp.async.cg.shared.global [%0], [%1], 16;" :: "r"(s), "l"(g));
}
__device__ __forceinline__ void ldm4(uint32_t r[4], uint32_t addr){
  asm volatile("ldmatrix.sync.aligned.m8n8.x4.shared.b16 {%0,%1,%2,%3}, [%4];"
    : "=r"(r[0]),"=r"(r[1]),"=r"(r[2]),"=r"(r[3]) : "r"(addr));
}
__device__ __forceinline__ void mma16816(float c[4], const uint32_t a[4],
                                         const uint32_t b[2]){
  asm volatile(
    "mma.sync.aligned.m16n8k16.row.col.f32.bf16.bf16.f32 "
    "{%0,%1,%2,%3}, {%4,%5,%6,%7}, {%8,%9}, {%0,%1,%2,%3};"
    : "+f"(c[0]),"+f"(c[1]),"+f"(c[2]),"+f"(c[3])
    : "r"(a[0]),"r"(a[1]),"r"(a[2]),"r"(a[3]), "r"(b[0]),"r"(b[1]));
}
__device__ __forceinline__ uint32_t pkbf2(float a, float b){
  __nv_bfloat162 t = __floats2bfloat162_rn(a, b);
  return *(uint32_t*)&t;
}

// ===========================================================================
// Prep: Hamilton-folded weights -> bf16 hi/lo
// ===========================================================================
__global__ void prep_weff_kernel(const float* __restrict__ w_qkv){
  int idx = blockIdx.x*256 + threadIdx.x;
  int g = idx >> 10, k = idx & 1023;
  int qc = g / 768, o = g - qc*768;
  int p = k >> 8, cch = k & 255;
  float w = c_SGN[qc*4+p] * w_qkv[(c_IDX[qc*4+p]*768 + o)*256 + cch];
  __nv_bfloat16 h = __float2bfloat16(w);
  g_WeffH[idx] = h;
  g_WeffL[idx] = __float2bfloat16(w - __bfloat162float(h));
}

__global__ void prep_wproj_kernel(const float* __restrict__ w_proj){
  int idx = blockIdx.x*256 + threadIdx.x;
  int g = idx >> 10, k = idx & 1023;
  int qc = g >> 8, o = g & 255;
  int p = k >> 8, cch = k & 255;
  float w = c_SGN[qc*4+p] * w_proj[(c_IDX[qc*4+p]*256 + o)*256 + cch];
  __nv_bfloat16 h = __float2bfloat16(w);
  g_WprojH[idx] = h;
  g_WprojL[idx] = __float2bfloat16(w - __bfloat162float(h));
}

// x (b, cch, p, n) fp32 -> XT (b, n, k=p*256+cch) bf16 hi/lo   (32x32 tiles)
__global__ void prep_xt_kernel(const float* __restrict__ x){
  __shared__ float sm[32][33];
  int b = blockIdx.z, k0 = blockIdx.x*32, n0 = blockIdx.y*32;
  int t = threadIdx.x;
  {
    int kk = t >> 3, n4 = (t & 7) << 2;
    int k = k0 + kk; int p = k >> 8, cch = k & 255;
    float4 v = *(const float4*)&x[((size_t)((b*CC+cch)*4 + p))*NPIX + n0 + n4];
    sm[kk][n4] = v.x; sm[kk][n4+1] = v.y; sm[kk][n4+2] = v.z; sm[kk][n4+3] = v.w;
  }
  __syncthreads();
  {
    int nn = t >> 3, k4 = (t & 7) << 2;
    float a[4]; uint32_t hp[2], lp[2];
    #pragma unroll
    for (int i=0;i<4;i++) a[i] = sm[k4+i][nn];
    __nv_bfloat16 hh[4];
    #pragma unroll
    for (int i=0;i<4;i++) hh[i] = __float2bfloat16(a[i]);
    hp[0] = pkbf2(__bfloat162float(hh[0]), __bfloat162float(hh[1]));
    hp[1] = pkbf2(__bfloat162float(hh[2]), __bfloat162float(hh[3]));
    lp[0] = pkbf2(a[0]-__bfloat162float(hh[0]), a[1]-__bfloat162float(hh[1]));
    lp[1] = pkbf2(a[2]-__bfloat162float(hh[2]), a[3]-__bfloat162float(hh[3]));
    size_t o = ((size_t)(b*NPIX) + n0 + nn)*DIM + k0 + k4;
    *(uint2*)&g_XTH[o] = make_uint2(hp[0], hp[1]);
    *(uint2*)&g_XTL[o] = make_uint2(lp[0], lp[1]);
  }
}

// ===========================================================================
// mma.sync GEMM: C(256m x 128n) per CTA, K=1024, bf16x3 split.
// MODE 0: A=Weff (M=3072), B=XT  -> scatter Q/K/V (+bias, Q pre-scaled)
// MODE 1: A=Wproj (M=1024), B=OT -> final output (+bias)
// ===========================================================================
#define AROWB 80
#define ATILE_B (256*AROWB)      // 20480
#define BTILE_B (128*AROWB)      // 10240
#define STAGE_B (2*ATILE_B + 2*BTILE_B)   // 61440
#define GEMM_SMEM (2*STAGE_B)    // 122880

template<int MODE>
__global__ __launch_bounds__(256, 1) void gemm_mma(const float* __restrict__ bias,
                                                   float* __restrict__ outp){
  extern __shared__ char smem[];
  const uint32_t sb = smem_u32(smem);

  const int tid = threadIdx.x;
  const int wid = tid >> 5, lane = tid & 31;
  const int m0 = blockIdx.x * 256;
  const int b  = blockIdx.y >> 3;
  const int n0 = (blockIdx.y & 7) << 7;
  const int wm = (wid >> 1) * 64;
  const int wn = (wid & 1) * 64;

  const __nv_bfloat16* Agh = (MODE==0 ? g_WeffH : g_WprojH) + (size_t)m0*DIM;
  const __nv_bfloat16* Agl = (MODE==0 ? g_WeffL : g_WprojL) + (size_t)m0*DIM;
  const __nv_bfloat16* Bgh = (MODE==0 ? g_XTH : g_OTH) + ((size_t)(b*NPIX) + n0)*DIM;
  const __nv_bfloat16* Bgl = (MODE==0 ? g_XTL : g_OTL) + ((size_t)(b*NPIX) + n0)*DIM;

  float acc[4][8][4];
  #pragma unroll
  for (int i=0;i<4;i++)
    #pragma unroll
    for (int j=0;j<8;j++)
      #pragma unroll
      for (int r=0;r<4;r++) acc[i][j][r] = 0.f;

  auto issue = [&](int kt, int buf){
    const uint32_t sbuf = sb + buf*STAGE_B;
    #pragma unroll
    for (int i=0;i<4;i++){               // A: 1024 16B-chunks per array
      int o = tid + i*256;
      int row = o >> 2, c16 = o & 3;
      size_t goff = (size_t)row*DIM + kt*32 + c16*8;
      uint32_t soff = row*AROWB + c16*16;
      cpasync16(sbuf + soff,           Agh + goff);
      cpasync16(sbuf + ATILE_B + soff, Agl + goff);
    }
    #pragma unroll
    for (int i=0;i<2;i++){               // B: 512 16B-chunks per array
      int o = tid + i*256;
      int row = o >> 2, c16 = o & 3;
      size_t goff = (size_t)row*DIM + kt*32 + c16*8;
      uint32_t soff = row*AROWB + c16*16;
      cpasync16(sbuf + 2*ATILE_B + soff,           Bgh + goff);
      cpasync16(sbuf + 2*ATILE_B + BTILE_B + soff, Bgl + goff);
    }
  };

  issue(0, 0);
  asm volatile("cp.async.commit_group;" ::: "memory");

  for (int kt = 0; kt < 32; kt++){
    if (kt + 1 < 32){
      issue(kt+1, (kt+1)&1);
      asm volatile("cp.async.commit_group;" ::: "memory");
      asm volatile("cp.async.wait_group 1;" ::: "memory");
    } else {
      asm volatile("cp.async.wait_group 0;" ::: "memory");
    }
    __syncthreads();

    const uint32_t Ah = sb + (kt&1)*STAGE_B;
    const uint32_t Al = Ah + ATILE_B;
    const uint32_t Bh = Ah + 2*ATILE_B;
    const uint32_t Bl = Bh + BTILE_B;

    #pragma unroll
    for (int ks = 0; ks < 2; ks++){
      uint32_t ah[4][4], al[4][4], bh[8][2], bl[8][2];
      #pragma unroll
      for (int mi = 0; mi < 4; mi++){
        uint32_t off = (uint32_t)(wm + mi*16 + (lane & 15))*AROWB
                     + ks*32 + (lane >> 4)*16;
        ldm4(ah[mi], Ah + off);
        ldm4(al[mi], Al + off);
      }
      #pragma unroll
      for (int np = 0; np < 4; np++){
        uint32_t off = (uint32_t)(wn + np*16 + (lane >> 4)*8 + (lane & 7))*AROWB
                     + ks*32 + ((lane >> 3) & 1)*16;
        uint32_t r[4];
        ldm4(r, Bh + off);
        bh[np*2][0]=r[0]; bh[np*2][1]=r[1]; bh[np*2+1][0]=r[2]; bh[np*2+1][1]=r[3];
        ldm4(r, Bl + off);
        bl[np*2][0]=r[0]; bl[np*2][1]=r[1]; bl[np*2+1][0]=r[2]; bl[np*2+1][1]=r[3];
      }
      #pragma unroll
      for (int mi=0;mi<4;mi++)
        #pragma unroll
        for (int ni=0;ni<8;ni++) mma16816(acc[mi][ni], ah[mi], bh[ni]);
      #pragma unroll
      for (int mi=0;mi<4;mi++)
        #pragma unroll
        for (int ni=0;ni<8;ni++) mma16816(acc[mi][ni], ah[mi], bl[ni]);
      #pragma unroll
      for (int mi=0;mi<4;mi++)
        #pragma unroll
        for (int ni=0;ni<8;ni++) mma16816(acc[mi][ni], al[mi], bh[ni]);
    }
    __syncthreads();
  }

  // ---- epilogue ----
  const float qscale = 0.08838834764831845f;  // 1/sqrt(128)
  #pragma unroll
  for (int mi=0;mi<4;mi++)
    #pragma unroll
    for (int half=0; half<2; half++){
      int gm = m0 + wm + mi*16 + (lane >> 2) + half*8;
      float bi = bias[gm];
      if (MODE==0){
        int qc = gm / 768; int o = gm - qc*768; int s3 = o >> 8; int cch = o & 255;
        int ch = (qc << 8) | cch; int hh = ch >> 7; int dd = ch & 127;
        float sc = (s3 == 0) ? qscale : 1.f;
        float* dst = (s3 == 0 ? g_Q : (s3 == 1 ? g_K : g_V))
                   + ((size_t)((b*HEADS + hh)*HD + dd))*NPIX;
        #pragma unroll
        for (int ni=0;ni<8;ni++){
          int nn = n0 + wn + ni*8 + (lane & 3)*2;
          float2 v = make_float2((acc[mi][ni][half*2+0] + bi)*sc,
                                 (acc[mi][ni][half*2+1] + bi)*sc);
          *(float2*)&dst[nn] = v;
        }
      } else {
        int qc = gm >> 8; int cch = gm & 255;
        float* dst = outp + ((size_t)((b*CC + cch)*4 + qc))*NPIX;
        #pragma unroll
        for (int ni=0;ni<8;ni++){
          int nn = n0 + wn + ni*8 + (lane & 3)*2;
          float2 v = make_float2(acc[mi][ni][half*2+0] + bi,
                                 acc[mi][ni][half*2+1] + bi);
          *(float2*)&dst[nn] = v;
        }
      }
    }
}

// ===========================================================================
// Convert Q,K (bh, d, N) fp32 -> (bh, n, d) bf16 hi/lo; Q additionally x log2e
// ===========================================================================
__global__ void conv_qk_kernel(){
  __shared__ float t[32][33];
  int bh = blockIdx.z;
  int d0 = blockIdx.x*32, n0 = blockIdx.y*32;
  int tid = threadIdx.x;
  #pragma unroll
  for (int which = 0; which < 2; which++){
    const float* src = (which ? g_K : g_Q) + (size_t)bh*HD*NPIX;
    __nv_bfloat16* dh = (which ? g_KTH : g_QTH) + (size_t)bh*NPIX*HD;
    __nv_bfloat16* dl = (which ? g_KTL : g_QTL) + (size_t)bh*NPIX*HD;
    float scl = which ? 1.f : 1.4426950408889634f;   // log2(e) folded into Q
    {
      int r = tid >> 3, c4 = (tid & 7) << 2;
      float4 v = *(const float4*)&src[(size_t)(d0+r)*NPIX + n0 + c4];
      t[r][c4+0] = v.x*scl; t[r][c4+1] = v.y*scl;
      t[r][c4+2] = v.z*scl; t[r][c4+3] = v.w*scl;
    }
    __syncthreads();
    {
      int nn = tid >> 3, dd4 = (tid & 7) << 2;
      float a[4];
      #pragma unroll
      for (int i=0;i<4;i++) a[i] = t[dd4+i][nn];
      __nv_bfloat16 hh[4];
      #pragma unroll
      for (int i=0;i<4;i++) hh[i] = __float2bfloat16(a[i]);
      size_t o = ((size_t)(n0+nn))*HD + d0 + dd4;
      *(uint2*)&dh[o] = make_uint2(
        pkbf2(__bfloat162float(hh[0]), __bfloat162float(hh[1])),
        pkbf2(__bfloat162float(hh[2]), __bfloat162float(hh[3])));
      *(uint2*)&dl[o] = make_uint2(
        pkbf2(a[0]-__bfloat162float(hh[0]), a[1]-__bfloat162float(hh[1])),
        pkbf2(a[2]-__bfloat162float(hh[2]), a[3]-__bfloat162float(hh[3])));
    }
    __syncthreads();
  }
}

// V (bh, d, N) fp32 -> bf16 hi/lo, same layout
__global__ void conv_v_kernel(){
  size_t idx = ((size_t)blockIdx.x*256 + threadIdx.x)*4;
  float4 v = *(const float4*)&g_V[idx];
  __nv_bfloat16 h0 = __float2bfloat16(v.x), h1 = __float2bfloat16(v.y);
  __nv_bfloat16 h2 = __float2bfloat16(v.z), h3 = __float2bfloat16(v.w);
  *(uint2*)&g_VH[idx] = make_uint2(
    pkbf2(__bfloat162float(h0), __bfloat162float(h1)),
    pkbf2(__bfloat162float(h2), __bfloat162float(h3)));
  *(uint2*)&g_VL[idx] = make_uint2(
    pkbf2(v.x-__bfloat162float(h0), v.y-__bfloat162float(h1)),
    pkbf2(v.z-__bfloat162float(h2), v.w-__bfloat162float(h3)));
}

// ===========================================================================
// Flash attention, mma.sync bf16x3. CTA = (b,h) x 128 queries, 256 thr,
// 8 warps x 16 q-rows. Q & P live in register fragments; K/V double-buffered.
// ===========================================================================
#define AT_KROW 272u
#define AT_VROW 144u
#define AT_KTILE (64u*AT_KROW)                 // 17408
#define AT_VTILE (128u*AT_VROW)                // 18432
#define AT_STAGE (2u*AT_KTILE + 2u*AT_VTILE)   // 71680
#define AT_SMEM  (2u*AT_STAGE)                 // 143360

__global__ __launch_bounds__(256, 1) void attn_mma(){
  extern __shared__ char smem[];
  const uint32_t sb = smem_u32(smem);
  const int tid = threadIdx.x;
  const int wid = tid >> 5, lane = tid & 31;
  const int bh = blockIdx.y;
  const int q0 = blockIdx.x * 128;
  const int b = bh >> 3, h = bh & 7;

  // ---- Load Q tile (128 x 128) hi/lo into smem (stage-0 region), then frags
  {
    const __nv_bfloat16* qh_g = g_QTH + ((size_t)bh*NPIX + q0)*HD;
    const __nv_bfloat16* ql_g = g_QTL + ((size_t)bh*NPIX + q0)*HD;
    #pragma unroll
    for (int i=0;i<8;i++){
      int o = tid + i*256;               // 2048 chunks
      int row = o >> 4, c = o & 15;
      cpasync16(sb + row*AT_KROW + c*16,               qh_g + (size_t)row*HD + c*8);
      cpasync16(sb + 128u*AT_KROW + row*AT_KROW + c*16, ql_g + (size_t)row*HD + c*8);
    }
    asm volatile("cp.async.commit_group;" ::: "memory");
    asm volatile("cp.async.wait_group 0;" ::: "memory");
    __syncthreads();
  }
  uint32_t qfh[8][4], qfl[8][4];
  #pragma unroll
  for (int kf=0; kf<8; kf++){
    uint32_t addr = sb + (uint32_t)(wid*16 + (lane & 15))*AT_KROW
                  + kf*32 + (lane >> 4)*16;
    ldm4(qfh[kf], addr);
    ldm4(qfl[kf], addr + 128u*AT_KROW);
  }
  __syncthreads();   // done with Q smem; reuse for K/V stages

  const __nv_bfloat16* kh_g = g_KTH + (size_t)bh*NPIX*HD;
  const __nv_bfloat16* kl_g = g_KTL + (size_t)bh*NPIX*HD;
  const __nv_bfloat16* vh_g = g_VH + (size_t)bh*HD*NPIX;
  const __nv_bfloat16* vl_g = g_VL + (size_t)bh*HD*NPIX;

  auto issueKV = [&](int kb, int buf){
    const uint32_t st = sb + buf*AT_STAGE;
    #pragma unroll
    for (int i=0;i<4;i++){              // K: 1024 chunks per array
      int o = tid + i*256;
      int row = o >> 4, c = o & 15;     // row<64 keys, 16 chunks of d
      size_t goff = (size_t)(kb*64 + row)*HD + c*8;
      cpasync16(st + row*AT_KROW + c*16,             kh_g + goff);
      cpasync16(st + AT_KTILE + row*AT_KROW + c*16,  kl_g + goff);
    }
    #pragma unroll
    for (int i=0;i<4;i++){              // V: 1024 chunks per array
      int o = tid + i*256;
      int row = o >> 3, c = o & 7;      // row<128 d, 8 chunks of keys
      size_t goff = (size_t)row*NPIX + kb*64 + c*8;
      cpasync16(st + 2u*AT_KTILE + row*AT_VROW + c*16,            vh_g + goff);
      cpasync16(st + 2u*AT_KTILE + AT_VTILE + row*AT_VROW + c*16, vl_g + goff);
    }
  };

  float accO[16][4];
  #pragma unroll
  for (int i=0;i<16;i++)
    #pragma unroll
    for (int r=0;r<4;r++) accO[i][r] = 0.f;
  float m0r = -1e30f, m1r = -1e30f, l0 = 0.f, l1 = 0.f;

  issueKV(0, 0);
  asm volatile("cp.async.commit_group;" ::: "memory");

  for (int kb = 0; kb < 16; kb++){
    if (kb + 1 < 16){
      issueKV(kb+1, (kb+1)&1);
      asm volatile("cp.async.commit_group;" ::: "memory");
      asm volatile("cp.async.wait_group 1;" ::: "memory");
    } else {
      asm volatile("cp.async.wait_group 0;" ::: "memory");
    }
    __syncthreads();
    const uint32_t st = sb + (kb&1)*AT_STAGE;

    // ---- S = Q K^T  (16q x 64k per warp), bf16x3
    float S[8][4];
    #pragma unroll
    for (int i=0;i<8;i++)
      #pragma unroll
      for (int r=0;r<4;r++) S[i][r] = 0.f;
    #pragma unroll
    for (int kf = 0; kf < 8; kf++){
      #pragma unroll
      for (int np = 0; np < 4; np++){
        uint32_t off = (uint32_t)(np*16 + (lane >> 4)*8 + (lane & 7))*AT_KROW
                     + kf*32 + ((lane >> 3) & 1)*16;
        uint32_t r[4];
        ldm4(r, st + off);
        uint32_t b0[2] = {r[0], r[1]}, b1[2] = {r[2], r[3]};
        mma16816(S[np*2],   qfh[kf], b0);
        mma16816(S[np*2+1], qfh[kf], b1);
        mma16816(S[np*2],   qfl[kf], b0);
        mma16816(S[np*2+1], qfl[kf], b1);
        ldm4(r, st + AT_KTILE + off);
        uint32_t c0[2] = {r[0], r[1]}, c1[2] = {r[2], r[3]};
        mma16816(S[np*2],   qfh[kf], c0);
        mma16816(S[np*2+1], qfh[kf], c1);
      }
    }

    // ---- online softmax (rows: r = lane>>2 and r+8); log2-domain
    float mx0 = -1e30f, mx1 = -1e30f;
    #pragma unroll
    for (int i=0;i<8;i++){
      mx0 = fmaxf(mx0, fmaxf(S[i][0], S[i][1]));
      mx1 = fmaxf(mx1, fmaxf(S[i][2], S[i][3]));
    }
    mx0 = fmaxf(mx0, __shfl_xor_sync(0xffffffffu, mx0, 1));
    mx0 = fmaxf(mx0, __shfl_xor_sync(0xffffffffu, mx0, 2));
    mx1 = fmaxf(mx1, __shfl_xor_sync(0xffffffffu, mx1, 1));
    mx1 = fmaxf(mx1, __shfl_xor_sync(0xffffffffu, mx1, 2));
    float mn0 = fmaxf(m0r, mx0), mn1 = fmaxf(m1r, mx1);
    float al0 = exp2f(m0r - mn0), al1 = exp2f(m1r - mn1);
    m0r = mn0; m1r = mn1;

    float rs0 = 0.f, rs1 = 0.f;
    uint32_t ph[4][4], pl[4][4];
    #pragma unroll
    for (int nf = 0; nf < 8; nf++){
      float p0 = exp2f(S[nf][0] - mn0);
      float p1 = exp2f(S[nf][1] - mn0);
      float p2 = exp2f(S[nf][2] - mn1);
      float p3 = exp2f(S[nf][3] - mn1);
      rs0 += p0 + p1; rs1 += p2 + p3;
      __nv_bfloat16 h0 = __float2bfloat16(p0), h1 = __float2bfloat16(p1);
      __nv_bfloat16 h2 = __float2bfloat16(p2), h3 = __float2bfloat16(p3);
      int kf = nf >> 1, pc = (nf & 1)*2;
      ph[kf][pc+0] = pkbf2(__bfloat162float(h0), __bfloat162float(h1));
      ph[kf][pc+1] = pkbf2(__bfloat162float(h2), __bfloat162float(h3));
      pl[kf][pc+0] = pkbf2(p0-__bfloat162float(h0), p1-__bfloat162float(h1));
      pl[kf][pc+1] = pkbf2(p2-__bfloat162float(h2), p3-__bfloat162float(h3));
    }
    rs0 += __shfl_xor_sync(0xffffffffu, rs0, 1);
    rs0 += __shfl_xor_sync(0xffffffffu, rs0, 2);
    rs1 += __shfl_xor_sync(0xffffffffu, rs1, 1);
    rs1 += __shfl_xor_sync(0xffffffffu, rs1, 2);
    l0 = l0*al0 + rs0; l1 = l1*al1 + rs1;

    #pragma unroll
    for (int i=0;i<16;i++){
      accO[i][0] *= al0; accO[i][1] *= al0;
      accO[i][2] *= al1; accO[i][3] *= al1;
    }

    // ---- accO += P V  (16q x 128d per warp), bf16x3
    const uint32_t vb = st + 2u*AT_KTILE;
    #pragma unroll
    for (int kf = 0; kf < 4; kf++){
      #pragma unroll
      for (int np = 0; np < 8; np++){
        uint32_t off = (uint32_t)(np*16 + (lane >> 4)*8 + (lane & 7))*AT_VROW
                     + kf*32 + ((lane >> 3) & 1)*16;
        uint32_t r[4];
        ldm4(r, vb + off);
        uint32_t b0[2] = {r[0], r[1]}, b1[2] = {r[2], r[3]};
        mma16816(accO[np*2],   ph[kf], b0);
        mma16816(accO[np*2+1], ph[kf], b1);
        mma16816(accO[np*2],   pl[kf], b0);
        mma16816(accO[np*2+1], pl[kf], b1);
        ldm4(r, vb + AT_VTILE + off);
        uint32_t c0[2] = {r[0], r[1]}, c1[2] = {r[2], r[3]};
        mma16816(accO[np*2],   ph[kf], c0);
        mma16816(accO[np*2+1], ph[kf], c1);
      }
    }
    __syncthreads();
  }

  // ---- epilogue: O = accO / l -> bf16 hi/lo at (b, n, ch)
  float inv0 = 1.f / l0, inv1 = 1.f / l1;
  int na = q0 + wid*16 + (lane >> 2);
  int nb2 = na + 8;
  #pragma unroll
  for (int nf = 0; nf < 16; nf++){
    int ch = h*HD + nf*8 + (lane & 3)*2;
    float v0 = accO[nf][0]*inv0, v1 = accO[nf][1]*inv0;
    float v2 = accO[nf][2]*inv1, v3 = accO[nf][3]*inv1;
    __nv_bfloat16 h0 = __float2bfloat16(v0), h1 = __float2bfloat16(v1);
    __nv_bfloat16 h2 = __float2bfloat16(v2), h3 = __float2bfloat16(v3);
    size_t oa = ((size_t)(b*NPIX) + na)*DIM + ch;
    size_t ob = ((size_t)(b*NPIX) + nb2)*DIM + ch;
    *(uint32_t*)&g_OTH[oa] = pkbf2(__bfloat162float(h0), __bfloat162float(h1));
    *(uint32_t*)&g_OTL[oa] = pkbf2(v0-__bfloat162float(h0), v1-__bfloat162float(h1));
    *(uint32_t*)&g_OTH[ob] = pkbf2(__bfloat162float(h2), __bfloat162float(h3));
    *(uint32_t*)&g_OTL[ob] = pkbf2(v2-__bfloat162float(h2), v3-__bfloat162float(h3));
  }
}

// ---------------------------------------------------------------------------
// Quaternion depthwise 3x3, accumulates into final output.
// ---------------------------------------------------------------------------
__global__ __launch_bounds__(256) void qdwconv_kernel(const float* __restrict__ x,
                                                      const float* __restrict__ w_pe,
                                                      const float* __restrict__ b_pe,
                                                      float* __restrict__ outp){
  __shared__ float xs[4][1024];
  __shared__ float wt[4][4][9];
  const int bid = blockIdx.x;
  const int c = bid & 255, b = bid >> 8;
  const int tid = threadIdx.x;

  #pragma unroll
  for (int p=0;p<4;p++){
    const float* xp = x + ((size_t)((b*CC + c)*4 + p))*NPIX;
    for (int k=tid; k<1024; k+=256) xs[p][k] = xp[k];
  }
  if (tid < 144){
    int qc = tid/36, p = (tid/9)&3, t = tid%9;
    wt[qc][p][t] = c_SGN[qc*4+p] * w_pe[(c_IDX[qc*4+p]*CC + c)*9 + t];
  }
  __syncthreads();

  float bia[4];
  #pragma unroll
  for (int qc=0;qc<4;qc++) bia[qc] = b_pe[qc*CC + c];

  for (int k=tid; k<1024; k+=256){
    int hh = k >> 5, ww = k & 31;
    float acc[4] = {bia[0],bia[1],bia[2],bia[3]};
    #pragma unroll
    for (int p=0;p<4;p++){
      #pragma unroll
      for (int kh=0;kh<3;kh++){
        int h2 = hh + kh - 1;
        if (h2 < 0 || h2 > 31) continue;
        #pragma unroll
        for (int kw=0;kw<3;kw++){
          int w2 = ww + kw - 1;
          if (w2 < 0 || w2 > 31) continue;
          float xv = xs[p][h2*32 + w2];
          #pragma unroll
          for (int qc=0;qc<4;qc++) acc[qc] = fmaf(wt[qc][p][kh*3+kw], xv, acc[qc]);
        }
      }
    }
    #pragma unroll
    for (int qc=0;qc<4;qc++)
      outp[((size_t)((b*CC + c)*4 + qc))*NPIX + k] += acc[qc];
  }
}

// ---------------------------------------------------------------------------
extern "C" void kernel_launch(void* const* d_in, const int* in_sizes, int n_in,
                              void* d_out, int out_size){
  const float* x      = (const float*)d_in[0];
  const float* w_qkv  = (const float*)d_in[1];
  const float* b_qkv  = (const float*)d_in[2];
  const float* w_proj = (const float*)d_in[3];
  const float* b_proj = (const float*)d_in[4];
  const float* w_pe   = (const float*)d_in[5];
  const float* b_pe   = (const float*)d_in[6];
  float* outp = (float*)d_out;

  (void)in_sizes; (void)n_in; (void)out_size;

  cudaFuncSetAttribute(gemm_mma<0>, cudaFuncAttributeMaxDynamicSharedMemorySize,
                       GEMM_SMEM);
  cudaFuncSetAttribute(gemm_mma<1>, cudaFuncAttributeMaxDynamicSharedMemorySize,
                       GEMM_SMEM);
  cudaFuncSetAttribute(attn_mma, cudaFuncAttributeMaxDynamicSharedMemorySize,
                       AT_SMEM);

  prep_weff_kernel <<< (MQKV*DIM)/256, 256 >>> (w_qkv);
  prep_wproj_kernel<<< (DIM*DIM)/256, 256 >>> (w_proj);
  prep_xt_kernel   <<< dim3(32,32,8), 256 >>> (x);

  // QKV: (3072 x 8192) mma.sync bf16x3
  gemm_mma<0><<< dim3(12,64), 256, GEMM_SMEM >>>(b_qkv, nullptr);

  // Convert Q/K (transpose) and V to bf16 hi/lo
  conv_qk_kernel<<< dim3(4,32,64), 256 >>>();
  conv_v_kernel <<< 8192, 256 >>>();

  // Attention: mma.sync flash, 8 q-tiles x 64 (b,h)
  attn_mma<<< dim3(8,64), 256, AT_SMEM >>>();

  // Proj: (1024 x 8192) mma.sync bf16x3 -> final output (+bias)
  gemm_mma<1><<< dim3(4,64), 256, GEMM_SMEM >>>(b_proj, outp);

  // Positional depthwise conv, accumulate
  qdwconv_kernel<<< NB*CC, 256 >>>(x, w_pe, b_pe, outp);
}

// round 5
// speedup vs baseline: 3.5688x; 1.2395x over previous
#include <cuda_runtime.h>
#include <cuda_bf16.h>
#include <cstdint>
#include <math.h>

#define NB 8
#define CC 256
#define NPIX 1024
#define HEADS 8
#define HD 128
#define MQKV 3072
#define DIM 1024

// Hamilton tables
__constant__ int   c_IDX[16] = {0,1,2,3, 1,0,3,2, 2,3,0,1, 3,2,1,0};
__constant__ float c_SGN[16] = {1.f,-1.f,-1.f,-1.f, 1.f,1.f,1.f,-1.f,
                                1.f,-1.f,1.f,1.f, 1.f,1.f,-1.f,1.f};

// Scratch (device globals). ALL tensor-core operands are stored PRE-TILED and
// PRE-SWIZZLED so kernels fetch whole tiles with single cp.async.bulk copies.
// GEMM A tiles: 256 rows x 64B (16KB), tile id = mtile*32 + kt
__device__ __nv_bfloat16 g_WeffH[(size_t)MQKV*DIM];
__device__ __nv_bfloat16 g_WeffL[(size_t)MQKV*DIM];
__device__ __nv_bfloat16 g_WprojH[(size_t)DIM*DIM];
__device__ __nv_bfloat16 g_WprojL[(size_t)DIM*DIM];
// GEMM B tiles: 128 rows x 64B (8KB), tile id = (b*8+ntile)*32 + kt
__device__ __nv_bfloat16 g_XTH[(size_t)NB*NPIX*DIM];
__device__ __nv_bfloat16 g_XTL[(size_t)NB*NPIX*DIM];
__device__ __nv_bfloat16 g_OTH[(size_t)NB*NPIX*DIM];
__device__ __nv_bfloat16 g_OTL[(size_t)NB*NPIX*DIM];
// fp32 intermediates from QKV GEMM
__device__ float g_Q[(size_t)NB*HEADS*HD*NPIX];        // (bh, d, N), Q pre-scaled
__device__ float g_K[(size_t)NB*HEADS*HD*NPIX];
__device__ float g_V[(size_t)NB*HEADS*HD*NPIX];
// attention tiles: Q/K 64 rows x 256B (16KB) per (bh, 64-block of n)
__device__ __nv_bfloat16 g_QTH[(size_t)NB*HEADS*NPIX*HD];
__device__ __nv_bfloat16 g_QTL[(size_t)NB*HEADS*NPIX*HD];
__device__ __nv_bfloat16 g_KTH[(size_t)NB*HEADS*NPIX*HD];
__device__ __nv_bfloat16 g_KTL[(size_t)NB*HEADS*NPIX*HD];
// V tiles: 128 rows(d) x 128B (16KB) per (bh, kb)
__device__ __nv_bfloat16 g_VH[(size_t)NB*HEADS*HD*NPIX];
__device__ __nv_bfloat16 g_VL[(size_t)NB*HEADS*HD*NPIX];

// ===========================================================================
// Helpers (base-ISA: cp.async.bulk / mbarrier / ldmatrix / mma.sync)
// ===========================================================================
__device__ __forceinline__ uint32_t smem_u32(const void* p){
  uint32_t a;
  asm("{ .reg .u64 t; cvta.to.shared.u64 t, %1; cvt.u32.u64 %0, t; }"
      : "=r"(a) : "l"(p));
  return a;
}
__device__ __forceinline__ void ldm4(uint32_t r[4], uint32_t addr){
  asm volatile("ldmatrix.sync.aligned.m8n8.x4.shared.b16 {%0,%1,%2,%3}, [%4];"
    : "=r"(r[0]),"=r"(r[1]),"=r"(r[2]),"=r"(r[3]) : "r"(addr));
}
__device__ __forceinline__ void mma16816(float c[4], const uint32_t a[4],
                                         const uint32_t b[2]){
  asm volatile(
    "mma.sync.aligned.m16n8k16.row.col.f32.bf16.bf16.f32 "
    "{%0,%1,%2,%3}, {%4,%5,%6,%7}, {%8,%9}, {%0,%1,%2,%3};"
    : "+f"(c[0]),"+f"(c[1]),"+f"(c[2]),"+f"(c[3])
    : "r"(a[0]),"r"(a[1]),"r"(a[2]),"r"(a[3]), "r"(b[0]),"r"(b[1]));
}
__device__ __forceinline__ uint32_t pkbf2(float a, float b){
  __nv_bfloat162 t = __floats2bfloat162_rn(a, b);
  return *(uint32_t*)&t;
}
#define BULKCP(dst, src, bytes, mb) \
  asm volatile("cp.async.bulk.shared::cluster.global.mbarrier::complete_tx::bytes [%0], [%1], %2, [%3];" \
    :: "r"((uint32_t)(dst)), "l"(src), "r"((uint32_t)(bytes)), "r"((uint32_t)(mb)) : "memory")
#define MBARRIER_INIT(mb, c) \
  asm volatile("mbarrier.init.shared.b64 [%0], %1;" :: "r"((uint32_t)(mb)), "r"((uint32_t)(c)) : "memory")
#define MBARRIER_EXPECT_TX(mb, tx) \
  asm volatile("mbarrier.arrive.expect_tx.shared.b64 _, [%0], %1;" :: "r"((uint32_t)(mb)), "r"((uint32_t)(tx)) : "memory")
#define MBARRIER_WAIT_PARITY(mb, ph) do { \
    uint32_t _m = (uint32_t)(mb); uint32_t _p = (uint32_t)(ph); uint32_t _d; \
    asm volatile("{\n\t.reg .pred p;\n\t" \
        "mbarrier.try_wait.parity.acquire.cta.shared::cta.b64 p, [%1], %2;\n\t" \
        "selp.b32 %0, 1, 0, p;\n\t}" : "=r"(_d) : "r"(_m), "r"(_p) : "memory"); \
    if (!_d) { \
      asm volatile("{\n\t.reg .pred P1;\n\t" \
        "WL_%=:\n\t" \
        "mbarrier.try_wait.parity.acquire.cta.shared::cta.b64 P1, [%0], %1, 0x989680;\n\t" \
        "@P1 bra.uni WD_%=;\n\t" \
        "bra.uni WL_%=;\n\t" \
        "WD_%=:\n\t}" :: "r"(_m), "r"(_p) : "memory"); \
    } \
  } while(0)

// swizzled byte offsets inside tiles (row-major rows of 64/128/256 bytes)
__device__ __forceinline__ uint32_t swz64 (uint32_t r, uint32_t c16){ return r*64u  + ((c16 ^ ((r>>1)&3u))<<4); }
__device__ __forceinline__ uint32_t swz128(uint32_t r, uint32_t c16){ return r*128u + ((c16 ^ (r&7u))<<4); }
__device__ __forceinline__ uint32_t swz256(uint32_t r, uint32_t c16){ return r*256u + ((c16 ^ (r&7u))<<4); }

// ===========================================================================
// Prep: Hamilton-folded weights -> bf16 hi/lo, tiled+swizzled
// ===========================================================================
__global__ void prep_w_kernel(const float* __restrict__ w,
                              __nv_bfloat16* __restrict__ outH,
                              __nv_bfloat16* __restrict__ outL, int is_qkv){
  int idx = blockIdx.x*256 + threadIdx.x;     // chunk id: M*128
  int g = idx >> 7, c = idx & 127;            // c = 16B chunk along k
  int k0 = c*8;
  int qc, o;
  if (is_qkv){ qc = g / 768; o = g - qc*768; } else { qc = g >> 8; o = g & 255; }
  int p = k0 >> 8, cch = k0 & 255;
  float s = c_SGN[qc*4+p];
  const float* src = w + ((size_t)(c_IDX[qc*4+p]*(is_qkv?768:256) + o))*256 + cch;
  float4 v0 = *(const float4*)src;
  float4 v1 = *(const float4*)(src+4);
  float a[8] = {v0.x*s,v0.y*s,v0.z*s,v0.w*s, v1.x*s,v1.y*s,v1.z*s,v1.w*s};
  __nv_bfloat16 h[8]; float hf[8];
  #pragma unroll
  for (int i=0;i<8;i++){ h[i] = __float2bfloat16(a[i]); hf[i] = __bfloat162float(h[i]); }
  uint4 H, L;
  H.x = ((uint32_t)__bfloat16_as_ushort(h[1])<<16)|__bfloat16_as_ushort(h[0]);
  H.y = ((uint32_t)__bfloat16_as_ushort(h[3])<<16)|__bfloat16_as_ushort(h[2]);
  H.z = ((uint32_t)__bfloat16_as_ushort(h[5])<<16)|__bfloat16_as_ushort(h[4]);
  H.w = ((uint32_t)__bfloat16_as_ushort(h[7])<<16)|__bfloat16_as_ushort(h[6]);
  L.x = pkbf2(a[0]-hf[0], a[1]-hf[1]);
  L.y = pkbf2(a[2]-hf[2], a[3]-hf[3]);
  L.z = pkbf2(a[4]-hf[4], a[5]-hf[5]);
  L.w = pkbf2(a[6]-hf[6], a[7]-hf[7]);
  size_t base = ((size_t)((g>>8)*32 + (c>>2)))*16384;
  uint32_t off = swz64(g & 255, c & 3);
  *(uint4*)((char*)outH + base + off) = H;
  *(uint4*)((char*)outL + base + off) = L;
}

// x (b, cch, p, n) fp32 -> XT tiles (b, ntile, kt) bf16 hi/lo
__global__ void prep_xt_kernel(const float* __restrict__ x){
  __shared__ float sm[32][33];
  int b = blockIdx.z, k0 = blockIdx.x*32, n0 = blockIdx.y*32;
  int t = threadIdx.x;
  {
    int kk = t >> 3, n4 = (t & 7) << 2;
    int k = k0 + kk; int p = k >> 8, cch = k & 255;
    float4 v = *(const float4*)&x[((size_t)((b*CC+cch)*4 + p))*NPIX + n0 + n4];
    sm[kk][n4] = v.x; sm[kk][n4+1] = v.y; sm[kk][n4+2] = v.z; sm[kk][n4+3] = v.w;
  }
  __syncthreads();
  {
    int nn = t >> 3, k4 = (t & 7) << 2;
    int n = n0 + nn;
    float a[4];
    #pragma unroll
    for (int i=0;i<4;i++) a[i] = sm[k4+i][nn];
    __nv_bfloat16 hh[4];
    #pragma unroll
    for (int i=0;i<4;i++) hh[i] = __float2bfloat16(a[i]);
    uint2 hp = make_uint2(pkbf2(__bfloat162float(hh[0]), __bfloat162float(hh[1])),
                          pkbf2(__bfloat162float(hh[2]), __bfloat162float(hh[3])));
    uint2 lp = make_uint2(pkbf2(a[0]-__bfloat162float(hh[0]), a[1]-__bfloat162float(hh[1])),
                          pkbf2(a[2]-__bfloat162float(hh[2]), a[3]-__bfloat162float(hh[3])));
    size_t tb = ((size_t)((b*8 + (n>>7))*32 + (k0>>5)))*8192;
    uint32_t off = swz64(n & 127, k4 >> 3) + ((k4 >> 2) & 1)*8;
    *(uint2*)((char*)g_XTH + tb + off) = hp;
    *(uint2*)((char*)g_XTL + tb + off) = lp;
  }
}

// ===========================================================================
// mma.sync GEMM: 256m x 128n per CTA, K=1024, bf16x3, bulk-copy fed.
// ===========================================================================
#define GSTG 49152u
#define GEMM_SMEM (1024u + 2u*GSTG)

template<int MODE>
__global__ __launch_bounds__(256, 1) void gemm_mma(const float* __restrict__ bias,
                                                   float* __restrict__ outp){
  extern __shared__ char smem[];
  const uint32_t sb = smem_u32(smem);
  const int tid = threadIdx.x;
  const int wid = tid >> 5, lane = tid & 31;
  const int mt = blockIdx.x;
  const int b  = blockIdx.y >> 3;
  const int nt = blockIdx.y & 7;
  const int m0 = mt*256, n0 = nt*128;
  const int wm = (wid >> 1) * 64;
  const int wn = (wid & 1) * 64;

  const char* Ahb = (const char*)(MODE==0 ? g_WeffH : g_WprojH) + (size_t)mt*32*16384;
  const char* Alb = (const char*)(MODE==0 ? g_WeffL : g_WprojL) + (size_t)mt*32*16384;
  const char* Bhb = (const char*)(MODE==0 ? g_XTH : g_OTH) + (size_t)((b*8+nt)*32)*8192;
  const char* Blb = (const char*)(MODE==0 ? g_XTL : g_OTL) + (size_t)((b*8+nt)*32)*8192;

  if (tid == 0){ MBARRIER_INIT(sb+8, 1); MBARRIER_INIT(sb+16, 1); }
  __syncthreads();

  float acc[4][8][4];
  #pragma unroll
  for (int i=0;i<4;i++)
    #pragma unroll
    for (int j=0;j<8;j++)
      #pragma unroll
      for (int r=0;r<4;r++) acc[i][j][r] = 0.f;

  auto issue = [&](int kt){
    if (tid == 0){
      int buf = kt & 1;
      uint32_t mb = sb + 8 + buf*8;
      MBARRIER_EXPECT_TX(mb, GSTG);
      uint32_t d = sb + 1024 + buf*GSTG;
      BULKCP(d,         Ahb + (size_t)kt*16384, 16384, mb);
      BULKCP(d+16384,   Alb + (size_t)kt*16384, 16384, mb);
      BULKCP(d+32768,   Bhb + (size_t)kt*8192,  8192,  mb);
      BULKCP(d+40960,   Blb + (size_t)kt*8192,  8192,  mb);
    }
  };

  issue(0);
  for (int kt = 0; kt < 32; kt++){
    if (kt + 1 < 32) issue(kt+1);
    MBARRIER_WAIT_PARITY(sb + 8 + (kt&1)*8, (kt>>1)&1);
    const uint32_t st = sb + 1024 + (kt&1)*GSTG;

    #pragma unroll
    for (int ks = 0; ks < 2; ks++){
      uint32_t ah[4][4], al[4][4], bh[8][2], bl[8][2];
      #pragma unroll
      for (int mi = 0; mi < 4; mi++){
        uint32_t row = wm + mi*16 + (lane & 15);
        uint32_t c16 = ks*2 + (lane >> 4);
        uint32_t addr = st + swz64(row, c16);
        ldm4(ah[mi], addr);
        ldm4(al[mi], addr + 16384);
      }
      #pragma unroll
      for (int np = 0; np < 4; np++){
        uint32_t row = wn + np*16 + (lane >> 4)*8 + (lane & 7);
        uint32_t c16 = ks*2 + ((lane >> 3) & 1);
        uint32_t addr = st + 32768 + swz64(row, c16);
        uint32_t r[4];
        ldm4(r, addr);
        bh[np*2][0]=r[0]; bh[np*2][1]=r[1]; bh[np*2+1][0]=r[2]; bh[np*2+1][1]=r[3];
        ldm4(r, addr + 8192);
        bl[np*2][0]=r[0]; bl[np*2][1]=r[1]; bl[np*2+1][0]=r[2]; bl[np*2+1][1]=r[3];
      }
      #pragma unroll
      for (int mi=0;mi<4;mi++)
        #pragma unroll
        for (int ni=0;ni<8;ni++) mma16816(acc[mi][ni], ah[mi], bh[ni]);
      #pragma unroll
      for (int mi=0;mi<4;mi++)
        #pragma unroll
        for (int ni=0;ni<8;ni++) mma16816(acc[mi][ni], ah[mi], bl[ni]);
      #pragma unroll
      for (int mi=0;mi<4;mi++)
        #pragma unroll
        for (int ni=0;ni<8;ni++) mma16816(acc[mi][ni], al[mi], bh[ni]);
    }
    __syncthreads();
  }

  // ---- epilogue: direct stores from fragments ----
  const float qscale = 0.08838834764831845f;  // 1/sqrt(128)
  #pragma unroll
  for (int mi=0;mi<4;mi++)
    #pragma unroll
    for (int half=0; half<2; half++){
      int gm = m0 + wm + mi*16 + (lane >> 2) + half*8;
      float bi = bias[gm];
      if (MODE==0){
        int qc = gm / 768; int o = gm - qc*768; int s3 = o >> 8; int cch = o & 255;
        int ch = (qc << 8) | cch; int hh = ch >> 7; int dd = ch & 127;
        float sc = (s3 == 0) ? qscale : 1.f;
        float* dst = (s3 == 0 ? g_Q : (s3 == 1 ? g_K : g_V))
                   + ((size_t)((b*HEADS + hh)*HD + dd))*NPIX;
        #pragma unroll
        for (int ni=0;ni<8;ni++){
          int nn = n0 + wn + ni*8 + (lane & 3)*2;
          float2 v = make_float2((acc[mi][ni][half*2+0] + bi)*sc,
                                 (acc[mi][ni][half*2+1] + bi)*sc);
          *(float2*)&dst[nn] = v;
        }
      } else {
        int qc = gm >> 8; int cch = gm & 255;
        float* dst = outp + ((size_t)((b*CC + cch)*4 + qc))*NPIX;
        #pragma unroll
        for (int ni=0;ni<8;ni++){
          int nn = n0 + wn + ni*8 + (lane & 3)*2;
          float2 v = make_float2(acc[mi][ni][half*2+0] + bi,
                                 acc[mi][ni][half*2+1] + bi);
          *(float2*)&dst[nn] = v;
        }
      }
    }
}

// ===========================================================================
// Convert Q,K (bh,d,N) fp32 -> tiled (bh, nblock) 64x256B bf16 hi/lo tiles
// Q additionally scaled by log2(e).
// ===========================================================================
__global__ void conv_qk_kernel(){
  __shared__ float t[32][33];
  int bh = blockIdx.z;
  int d0 = blockIdx.x*32, n0 = blockIdx.y*32;
  int tid = threadIdx.x;
  #pragma unroll
  for (int which = 0; which < 2; which++){
    const float* src = (which ? g_K : g_Q) + (size_t)bh*HD*NPIX;
    char* dh = (char*)(which ? g_KTH : g_QTH);
    char* dl = (char*)(which ? g_KTL : g_QTL);
    float scl = which ? 1.f : 1.4426950408889634f;
    {
      int r = tid >> 3, c4 = (tid & 7) << 2;
      float4 v = *(const float4*)&src[(size_t)(d0+r)*NPIX + n0 + c4];
      t[r][c4+0] = v.x*scl; t[r][c4+1] = v.y*scl;
      t[r][c4+2] = v.z*scl; t[r][c4+3] = v.w*scl;
    }
    __syncthreads();
    {
      int nn = tid >> 3, dd4 = (tid & 7) << 2;
      int n = n0 + nn;
      float a[4];
      #pragma unroll
      for (int i=0;i<4;i++) a[i] = t[dd4+i][nn];
      __nv_bfloat16 hh[4];
      #pragma unroll
      for (int i=0;i<4;i++) hh[i] = __float2bfloat16(a[i]);
      uint2 hp = make_uint2(pkbf2(__bfloat162float(hh[0]), __bfloat162float(hh[1])),
                            pkbf2(__bfloat162float(hh[2]), __bfloat162float(hh[3])));
      uint2 lp = make_uint2(pkbf2(a[0]-__bfloat162float(hh[0]), a[1]-__bfloat162float(hh[1])),
                            pkbf2(a[2]-__bfloat162float(hh[2]), a[3]-__bfloat162float(hh[3])));
      size_t tb = ((size_t)bh*16 + (n>>6))*16384;
      uint32_t off = swz256(n & 63, (d0+dd4) >> 3) + ((dd4 >> 2) & 1)*8;
      *(uint2*)(dh + tb + off) = hp;
      *(uint2*)(dl + tb + off) = lp;
    }
    __syncthreads();
  }
}

// V (bh,d,N) fp32 -> tiled (bh, kb) 128x128B bf16 hi/lo
__global__ void conv_v_kernel(){
  size_t idx = ((size_t)blockIdx.x*256 + threadIdx.x)*4;
  int n = (int)(idx & 1023);
  int d = (int)((idx >> 10) & 127);
  int bh = (int)(idx >> 17);
  float4 v = *(const float4*)&g_V[idx];
  __nv_bfloat16 h0 = __float2bfloat16(v.x), h1 = __float2bfloat16(v.y);
  __nv_bfloat16 h2 = __float2bfloat16(v.z), h3 = __float2bfloat16(v.w);
  uint2 hp = make_uint2(pkbf2(__bfloat162float(h0), __bfloat162float(h1)),
                        pkbf2(__bfloat162float(h2), __bfloat162float(h3)));
  uint2 lp = make_uint2(pkbf2(v.x-__bfloat162float(h0), v.y-__bfloat162float(h1)),
                        pkbf2(v.z-__bfloat162float(h2), v.w-__bfloat162float(h3)));
  size_t tb = ((size_t)bh*16 + (n>>6))*16384;
  uint32_t off = swz128(d, (n & 63) >> 3) + ((n >> 2) & 1)*8;
  *(uint2*)((char*)g_VH + tb + off) = hp;
  *(uint2*)((char*)g_VL + tb + off) = lp;
}

// ===========================================================================
// Flash attention, mma.sync bf16x3, bulk-copy fed.
// CTA = (b,h) x 128 queries, 256 thr, 8 warps x 16 q-rows.
// ===========================================================================
#define ASTG 65536u
#define AT_SMEM (1024u + 2u*ASTG)

__global__ __launch_bounds__(256, 1) void attn_mma(){
  extern __shared__ char smem[];
  const uint32_t sb = smem_u32(smem);
  const int tid = threadIdx.x;
  const int wid = tid >> 5, lane = tid & 31;
  const int bh = blockIdx.y;
  const int qi = blockIdx.x;           // q block of 128
  const int q0 = qi * 128;
  const int b = bh >> 3, h = bh & 7;

  if (tid == 0){
    MBARRIER_INIT(sb+8, 1); MBARRIER_INIT(sb+16, 1); MBARRIER_INIT(sb+24, 1);
  }
  __syncthreads();

  // ---- Q load: 2 tiles hi + 2 tiles lo = 64KB into stage0 region
  if (tid == 0){
    MBARRIER_EXPECT_TX(sb+24, 65536);
    const char* qh_g = (const char*)g_QTH + ((size_t)bh*16 + qi*2)*16384;
    const char* ql_g = (const char*)g_QTL + ((size_t)bh*16 + qi*2)*16384;
    BULKCP(sb+1024,         qh_g, 32768, sb+24);
    BULKCP(sb+1024+32768,   ql_g, 32768, sb+24);
  }
  MBARRIER_WAIT_PARITY(sb+24, 0);

  uint32_t qfh[8][4], qfl[8][4];
  {
    uint32_t row = wid*16 + (lane & 15);
    uint32_t base = sb + 1024 + (row >> 6)*16384;
    uint32_t r6 = row & 63;
    #pragma unroll
    for (int kf = 0; kf < 8; kf++){
      uint32_t c16 = kf*2 + (lane >> 4);
      uint32_t addr = base + swz256(r6, c16);
      ldm4(qfh[kf], addr);
      ldm4(qfl[kf], addr + 32768);
    }
  }
  __syncthreads();   // Q consumed; stage0 reusable

  const char* kh_g = (const char*)g_KTH + (size_t)bh*16*16384;
  const char* kl_g = (const char*)g_KTL + (size_t)bh*16*16384;
  const char* vh_g = (const char*)g_VH  + (size_t)bh*16*16384;
  const char* vl_g = (const char*)g_VL  + (size_t)bh*16*16384;

  auto issueKV = [&](int kb){
    if (tid == 0){
      int buf = kb & 1;
      uint32_t mb = sb + 8 + buf*8;
      MBARRIER_EXPECT_TX(mb, ASTG);
      uint32_t d = sb + 1024 + buf*ASTG;
      BULKCP(d,         kh_g + (size_t)kb*16384, 16384, mb);
      BULKCP(d+16384,   kl_g + (size_t)kb*16384, 16384, mb);
      BULKCP(d+32768,   vh_g + (size_t)kb*16384, 16384, mb);
      BULKCP(d+49152,   vl_g + (size_t)kb*16384, 16384, mb);
    }
  };

  float accO[16][4];
  #pragma unroll
  for (int i=0;i<16;i++)
    #pragma unroll
    for (int r=0;r<4;r++) accO[i][r] = 0.f;
  float m0r = -1e30f, m1r = -1e30f, l0 = 0.f, l1 = 0.f;

  issueKV(0);
  for (int kb = 0; kb < 16; kb++){
    if (kb + 1 < 16) issueKV(kb+1);
    MBARRIER_WAIT_PARITY(sb + 8 + (kb&1)*8, (kb>>1)&1);
    const uint32_t st = sb + 1024 + (kb&1)*ASTG;

    // ---- S = Q K^T  (16q x 64k per warp), bf16x3
    float S[8][4];
    #pragma unroll
    for (int i=0;i<8;i++)
      #pragma unroll
      for (int r=0;r<4;r++) S[i][r] = 0.f;
    #pragma unroll
    for (int kf = 0; kf < 8; kf++){
      #pragma unroll
      for (int np = 0; np < 4; np++){
        uint32_t row = np*16 + (lane >> 4)*8 + (lane & 7);
        uint32_t c16 = kf*2 + ((lane >> 3) & 1);
        uint32_t addr = st + swz256(row, c16);
        uint32_t r[4];
        ldm4(r, addr);
        uint32_t b0[2] = {r[0], r[1]}, b1[2] = {r[2], r[3]};
        mma16816(S[np*2],   qfh[kf], b0);
        mma16816(S[np*2+1], qfh[kf], b1);
        mma16816(S[np*2],   qfl[kf], b0);
        mma16816(S[np*2+1], qfl[kf], b1);
        ldm4(r, addr + 16384);
        uint32_t c0[2] = {r[0], r[1]}, c1[2] = {r[2], r[3]};
        mma16816(S[np*2],   qfh[kf], c0);
        mma16816(S[np*2+1], qfh[kf], c1);
      }
    }

    // ---- online softmax (log2 domain; log2e folded into Q)
    float mx0 = -1e30f, mx1 = -1e30f;
    #pragma unroll
    for (int i=0;i<8;i++){
      mx0 = fmaxf(mx0, fmaxf(S[i][0], S[i][1]));
      mx1 = fmaxf(mx1, fmaxf(S[i][2], S[i][3]));
    }
    mx0 = fmaxf(mx0, __shfl_xor_sync(0xffffffffu, mx0, 1));
    mx0 = fmaxf(mx0, __shfl_xor_sync(0xffffffffu, mx0, 2));
    mx1 = fmaxf(mx1, __shfl_xor_sync(0xffffffffu, mx1, 1));
    mx1 = fmaxf(mx1, __shfl_xor_sync(0xffffffffu, mx1, 2));
    float mn0 = fmaxf(m0r, mx0), mn1 = fmaxf(m1r, mx1);
    float al0 = exp2f(m0r - mn0), al1 = exp2f(m1r - mn1);
    m0r = mn0; m1r = mn1;

    float rs0 = 0.f, rs1 = 0.f;
    uint32_t ph[4][4], pl[4][4];
    #pragma unroll
    for (int nf = 0; nf < 8; nf++){
      float p0 = exp2f(S[nf][0] - mn0);
      float p1 = exp2f(S[nf][1] - mn0);
      float p2 = exp2f(S[nf][2] - mn1);
      float p3 = exp2f(S[nf][3] - mn1);
      rs0 += p0 + p1; rs1 += p2 + p3;
      __nv_bfloat16 h0 = __float2bfloat16(p0), h1 = __float2bfloat16(p1);
      __nv_bfloat16 h2 = __float2bfloat16(p2), h3 = __float2bfloat16(p3);
      int kf = nf >> 1, pc = (nf & 1)*2;
      ph[kf][pc+0] = pkbf2(__bfloat162float(h0), __bfloat162float(h1));
      ph[kf][pc+1] = pkbf2(__bfloat162float(h2), __bfloat162float(h3));
      pl[kf][pc+0] = pkbf2(p0-__bfloat162float(h0), p1-__bfloat162float(h1));
      pl[kf][pc+1] = pkbf2(p2-__bfloat162float(h2), p3-__bfloat162float(h3));
    }
    rs0 += __shfl_xor_sync(0xffffffffu, rs0, 1);
    rs0 += __shfl_xor_sync(0xffffffffu, rs0, 2);
    rs1 += __shfl_xor_sync(0xffffffffu, rs1, 1);
    rs1 += __shfl_xor_sync(0xffffffffu, rs1, 2);
    l0 = l0*al0 + rs0; l1 = l1*al1 + rs1;

    #pragma unroll
    for (int i=0;i<16;i++){
      accO[i][0] *= al0; accO[i][1] *= al0;
      accO[i][2] *= al1; accO[i][3] *= al1;
    }

    // ---- accO += P V  (16q x 128d per warp), bf16x3
    const uint32_t vb = st + 32768;
    #pragma unroll
    for (int kf = 0; kf < 4; kf++){
      #pragma unroll
      for (int np = 0; np < 8; np++){
        uint32_t row = np*16 + (lane >> 4)*8 + (lane & 7);
        uint32_t c16 = kf*2 + ((lane >> 3) & 1);
        uint32_t addr = vb + swz128(row, c16);
        uint32_t r[4];
        ldm4(r, addr);
        uint32_t b0[2] = {r[0], r[1]}, b1[2] = {r[2], r[3]};
        mma16816(accO[np*2],   ph[kf], b0);
        mma16816(accO[np*2+1], ph[kf], b1);
        mma16816(accO[np*2],   pl[kf], b0);
        mma16816(accO[np*2+1], pl[kf], b1);
        ldm4(r, addr + 16384);
        uint32_t c0[2] = {r[0], r[1]}, c1[2] = {r[2], r[3]};
        mma16816(accO[np*2],   ph[kf], c0);
        mma16816(accO[np*2+1], ph[kf], c1);
      }
    }
    __syncthreads();
  }

  // ---- epilogue: O/l -> bf16 hi/lo into tiled OT
  float inv0 = 1.f / l0, inv1 = 1.f / l1;
  int na = q0 + wid*16 + (lane >> 2);
  int nb2 = na + 8;
  #pragma unroll
  for (int nf = 0; nf < 16; nf++){
    int ch = h*HD + nf*8 + (lane & 3)*2;
    float v0 = accO[nf][0]*inv0, v1 = accO[nf][1]*inv0;
    float v2 = accO[nf][2]*inv1, v3 = accO[nf][3]*inv1;
    __nv_bfloat16 h0 = __float2bfloat16(v0), h1 = __float2bfloat16(v1);
    __nv_bfloat16 h2 = __float2bfloat16(v2), h3 = __float2bfloat16(v3);
    size_t tba = ((size_t)((b*8 + (na>>7))*32 + (ch>>5)))*8192;
    size_t tbb = ((size_t)((b*8 + (nb2>>7))*32 + (ch>>5)))*8192;
    uint32_t ofa = swz64(na & 127, (ch>>3)&3) + (ch&7)*2;
    uint32_t ofb = swz64(nb2 & 127, (ch>>3)&3) + (ch&7)*2;
    *(uint32_t*)((char*)g_OTH + tba + ofa) = pkbf2(__bfloat162float(h0), __bfloat162float(h1));
    *(uint32_t*)((char*)g_OTL + tba + ofa) = pkbf2(v0-__bfloat162float(h0), v1-__bfloat162float(h1));
    *(uint32_t*)((char*)g_OTH + tbb + ofb) = pkbf2(__bfloat162float(h2), __bfloat162float(h3));
    *(uint32_t*)((char*)g_OTL + tbb + ofb) = pkbf2(v2-__bfloat162float(h2), v3-__bfloat162float(h3));
  }
}

// ---------------------------------------------------------------------------
// Quaternion depthwise 3x3, accumulates into final output.
// ---------------------------------------------------------------------------
__global__ __launch_bounds__(256) void qdwconv_kernel(const float* __restrict__ x,
                                                      const float* __restrict__ w_pe,
                                                      const float* __restrict__ b_pe,
                                                      float* __restrict__ outp){
  __shared__ float xs[4][1024];
  __shared__ float wt[4][4][9];
  const int bid = blockIdx.x;
  const int c = bid & 255, b = bid >> 8;
  const int tid = threadIdx.x;

  #pragma unroll
  for (int p=0;p<4;p++){
    const float* xp = x + ((size_t)((b*CC + c)*4 + p))*NPIX;
    for (int k=tid; k<1024; k+=256) xs[p][k] = xp[k];
  }
  if (tid < 144){
    int qc = tid/36, p = (tid/9)&3, t = tid%9;
    wt[qc][p][t] = c_SGN[qc*4+p] * w_pe[(c_IDX[qc*4+p]*CC + c)*9 + t];
  }
  __syncthreads();

  float bia[4];
  #pragma unroll
  for (int qc=0;qc<4;qc++) bia[qc] = b_pe[qc*CC + c];

  for (int k=tid; k<1024; k+=256){
    int hh = k >> 5, ww = k & 31;
    float acc[4] = {bia[0],bia[1],bia[2],bia[3]};
    #pragma unroll
    for (int p=0;p<4;p++){
      #pragma unroll
      for (int kh=0;kh<3;kh++){
        int h2 = hh + kh - 1;
        if (h2 < 0 || h2 > 31) continue;
        #pragma unroll
        for (int kw=0;kw<3;kw++){
          int w2 = ww + kw - 1;
          if (w2 < 0 || w2 > 31) continue;
          float xv = xs[p][h2*32 + w2];
          #pragma unroll
          for (int qc=0;qc<4;qc++) acc[qc] = fmaf(wt[qc][p][kh*3+kw], xv, acc[qc]);
        }
      }
    }
    #pragma unroll
    for (int qc=0;qc<4;qc++)
      outp[((size_t)((b*CC + c)*4 + qc))*NPIX + k] += acc[qc];
  }
}

// ---------------------------------------------------------------------------
extern "C" void kernel_launch(void* const* d_in, const int* in_sizes, int n_in,
                              void* d_out, int out_size){
  const float* x      = (const float*)d_in[0];
  const float* w_qkv  = (const float*)d_in[1];
  const float* b_qkv  = (const float*)d_in[2];
  const float* w_proj = (const float*)d_in[3];
  const float* b_proj = (const float*)d_in[4];
  const float* w_pe   = (const float*)d_in[5];
  const float* b_pe   = (const float*)d_in[6];
  float* outp = (float*)d_out;

  (void)in_sizes; (void)n_in; (void)out_size;

  cudaFuncSetAttribute(gemm_mma<0>, cudaFuncAttributeMaxDynamicSharedMemorySize,
                       GEMM_SMEM);
  cudaFuncSetAttribute(gemm_mma<1>, cudaFuncAttributeMaxDynamicSharedMemorySize,
                       GEMM_SMEM);
  cudaFuncSetAttribute(attn_mma, cudaFuncAttributeMaxDynamicSharedMemorySize,
                       AT_SMEM);

  // Weight prep (tiled + swizzled, bf16 hi/lo)
  __nv_bfloat16 *weffH, *weffL, *wprojH, *wprojL;
  cudaGetSymbolAddress((void**)&weffH, g_WeffH);
  cudaGetSymbolAddress((void**)&weffL, g_WeffL);
  cudaGetSymbolAddress((void**)&wprojH, g_WprojH);
  cudaGetSymbolAddress((void**)&wprojL, g_WprojL);
  prep_w_kernel<<< MQKV*128/256, 256 >>>(w_qkv, weffH, weffL, 1);
  prep_w_kernel<<< DIM*128/256, 256 >>>(w_proj, wprojH, wprojL, 0);
  prep_xt_kernel<<< dim3(32,32,8), 256 >>>(x);

  // QKV: (3072 x 8192) mma.sync bf16x3, bulk-fed
  gemm_mma<0><<< dim3(12,64), 256, GEMM_SMEM >>>(b_qkv, nullptr);

  // Convert Q/K (transpose+tile) and V (tile) to bf16 hi/lo
  conv_qk_kernel<<< dim3(4,32,64), 256 >>>();
  conv_v_kernel <<< 8192, 256 >>>();

  // Attention: mma.sync flash, 8 q-tiles x 64 (b,h)
  attn_mma<<< dim3(8,64), 256, AT_SMEM >>>();

  // Proj: (1024 x 8192) mma.sync bf16x3 -> final output (+bias)
  gemm_mma<1><<< dim3(4,64), 256, GEMM_SMEM >>>(b_proj, outp);

  // Positional depthwise conv, accumulate
  qdwconv_kernel<<< NB*CC, 256 >>>(x, w_pe, b_pe, outp);
}

// round 6
// speedup vs baseline: 3.6679x; 1.0278x over previous
#include <cuda_runtime.h>
#include <cuda_bf16.h>
#include <cstdint>
#include <math.h>

#define NB 8
#define CC 256
#define NPIX 1024
#define HEADS 8
#define HD 128
#define MQKV 3072
#define DIM 1024

// Hamilton tables
__constant__ int   c_IDX[16] = {0,1,2,3, 1,0,3,2, 2,3,0,1, 3,2,1,0};
__constant__ float c_SGN[16] = {1.f,-1.f,-1.f,-1.f, 1.f,1.f,1.f,-1.f,
                                1.f,-1.f,1.f,1.f, 1.f,1.f,-1.f,1.f};

// Scratch (device globals). ALL tensor-core operands pre-tiled + pre-swizzled
// so kernels fetch whole tiles with single cp.async.bulk copies.
// GEMM A tiles: 256 rows x 64B (16KB), tile id = mtile*32 + kt
__device__ __nv_bfloat16 g_WeffH[(size_t)MQKV*DIM];
__device__ __nv_bfloat16 g_WeffL[(size_t)MQKV*DIM];
__device__ __nv_bfloat16 g_WprojH[(size_t)DIM*DIM];
__device__ __nv_bfloat16 g_WprojL[(size_t)DIM*DIM];
// GEMM B tiles: 128 rows x 64B (8KB), tile id = (b*8+ntile)*32 + kt
__device__ __nv_bfloat16 g_XTH[(size_t)NB*NPIX*DIM];
__device__ __nv_bfloat16 g_XTL[(size_t)NB*NPIX*DIM];
__device__ __nv_bfloat16 g_OTH[(size_t)NB*NPIX*DIM];
__device__ __nv_bfloat16 g_OTL[(size_t)NB*NPIX*DIM];
// attention tiles: Q/K 64 rows(n) x 256B(d) (16KB) per (bh, nblock)
__device__ __nv_bfloat16 g_QTH[(size_t)NB*HEADS*NPIX*HD];
__device__ __nv_bfloat16 g_QTL[(size_t)NB*HEADS*NPIX*HD];
__device__ __nv_bfloat16 g_KTH[(size_t)NB*HEADS*NPIX*HD];
__device__ __nv_bfloat16 g_KTL[(size_t)NB*HEADS*NPIX*HD];
// V tiles: 128 rows(d) x 128B(n) (16KB) per (bh, kb)
__device__ __nv_bfloat16 g_VH[(size_t)NB*HEADS*HD*NPIX];
__device__ __nv_bfloat16 g_VL[(size_t)NB*HEADS*HD*NPIX];

// ===========================================================================
// Helpers (base-ISA: cp.async.bulk / mbarrier / ldmatrix / mma.sync)
// ===========================================================================
__device__ __forceinline__ uint32_t smem_u32(const void* p){
  uint32_t a;
  asm("{ .reg .u64 t; cvta.to.shared.u64 t, %1; cvt.u32.u64 %0, t; }"
      : "=r"(a) : "l"(p));
  return a;
}
__device__ __forceinline__ void ldm4(uint32_t r[4], uint32_t addr){
  asm volatile("ldmatrix.sync.aligned.m8n8.x4.shared.b16 {%0,%1,%2,%3}, [%4];"
    : "=r"(r[0]),"=r"(r[1]),"=r"(r[2]),"=r"(r[3]) : "r"(addr));
}
__device__ __forceinline__ void mma16816(float c[4], const uint32_t a[4],
                                         const uint32_t b[2]){
  asm volatile(
    "mma.sync.aligned.m16n8k16.row.col.f32.bf16.bf16.f32 "
    "{%0,%1,%2,%3}, {%4,%5,%6,%7}, {%8,%9}, {%0,%1,%2,%3};"
    : "+f"(c[0]),"+f"(c[1]),"+f"(c[2]),"+f"(c[3])
    : "r"(a[0]),"r"(a[1]),"r"(a[2]),"r"(a[3]), "r"(b[0]),"r"(b[1]));
}
__device__ __forceinline__ uint32_t pkbf2(float a, float b){
  __nv_bfloat162 t = __floats2bfloat162_rn(a, b);
  return *(uint32_t*)&t;
}
#define BULKCP(dst, src, bytes, mb) \
  asm volatile("cp.async.bulk.shared::cluster.global.mbarrier::complete_tx::bytes [%0], [%1], %2, [%3];" \
    :: "r"((uint32_t)(dst)), "l"(src), "r"((uint32_t)(bytes)), "r"((uint32_t)(mb)) : "memory")
#define MBARRIER_INIT(mb, c) \
  asm volatile("mbarrier.init.shared.b64 [%0], %1;" :: "r"((uint32_t)(mb)), "r"((uint32_t)(c)) : "memory")
#define MBARRIER_EXPECT_TX(mb, tx) \
  asm volatile("mbarrier.arrive.expect_tx.shared.b64 _, [%0], %1;" :: "r"((uint32_t)(mb)), "r"((uint32_t)(tx)) : "memory")
#define MBARRIER_WAIT_PARITY(mb, ph) do { \
    uint32_t _m = (uint32_t)(mb); uint32_t _p = (uint32_t)(ph); uint32_t _d; \
    asm volatile("{\n\t.reg .pred p;\n\t" \
        "mbarrier.try_wait.parity.acquire.cta.shared::cta.b64 p, [%1], %2;\n\t" \
        "selp.b32 %0, 1, 0, p;\n\t}" : "=r"(_d) : "r"(_m), "r"(_p) : "memory"); \
    if (!_d) { \
      asm volatile("{\n\t.reg .pred P1;\n\t" \
        "WL_%=:\n\t" \
        "mbarrier.try_wait.parity.acquire.cta.shared::cta.b64 P1, [%0], %1, 0x989680;\n\t" \
        "@P1 bra.uni WD_%=;\n\t" \
        "bra.uni WL_%=;\n\t" \
        "WD_%=:\n\t}" :: "r"(_m), "r"(_p) : "memory"); \
    } \
  } while(0)

// swizzled byte offsets inside tiles (row-major rows of 64/128/256 bytes)
__device__ __forceinline__ uint32_t swz64 (uint32_t r, uint32_t c16){ return r*64u  + ((c16 ^ ((r>>1)&3u))<<4); }
__device__ __forceinline__ uint32_t swz128(uint32_t r, uint32_t c16){ return r*128u + ((c16 ^ (r&7u))<<4); }
__device__ __forceinline__ uint32_t swz256(uint32_t r, uint32_t c16){ return r*256u + ((c16 ^ (r&7u))<<4); }

// ===========================================================================
// Prep: Hamilton-folded weights -> bf16 hi/lo, tiled+swizzled
// ===========================================================================
__global__ void prep_w_kernel(const float* __restrict__ w,
                              __nv_bfloat16* __restrict__ outH,
                              __nv_bfloat16* __restrict__ outL, int is_qkv){
  int idx = blockIdx.x*256 + threadIdx.x;     // chunk id: M*128
  int g = idx >> 7, c = idx & 127;            // c = 16B chunk along k
  int k0 = c*8;
  int qc, o;
  if (is_qkv){ qc = g / 768; o = g - qc*768; } else { qc = g >> 8; o = g & 255; }
  int p = k0 >> 8, cch = k0 & 255;
  float s = c_SGN[qc*4+p];
  const float* src = w + ((size_t)(c_IDX[qc*4+p]*(is_qkv?768:256) + o))*256 + cch;
  float4 v0 = *(const float4*)src;
  float4 v1 = *(const float4*)(src+4);
  float a[8] = {v0.x*s,v0.y*s,v0.z*s,v0.w*s, v1.x*s,v1.y*s,v1.z*s,v1.w*s};
  __nv_bfloat16 h[8]; float hf[8];
  #pragma unroll
  for (int i=0;i<8;i++){ h[i] = __float2bfloat16(a[i]); hf[i] = __bfloat162float(h[i]); }
  uint4 H, L;
  H.x = ((uint32_t)__bfloat16_as_ushort(h[1])<<16)|__bfloat16_as_ushort(h[0]);
  H.y = ((uint32_t)__bfloat16_as_ushort(h[3])<<16)|__bfloat16_as_ushort(h[2]);
  H.z = ((uint32_t)__bfloat16_as_ushort(h[5])<<16)|__bfloat16_as_ushort(h[4]);
  H.w = ((uint32_t)__bfloat16_as_ushort(h[7])<<16)|__bfloat16_as_ushort(h[6]);
  L.x = pkbf2(a[0]-hf[0], a[1]-hf[1]);
  L.y = pkbf2(a[2]-hf[2], a[3]-hf[3]);
  L.z = pkbf2(a[4]-hf[4], a[5]-hf[5]);
  L.w = pkbf2(a[6]-hf[6], a[7]-hf[7]);
  size_t base = ((size_t)((g>>8)*32 + (c>>2)))*16384;
  uint32_t off = swz64(g & 255, c & 3);
  *(uint4*)((char*)outH + base + off) = H;
  *(uint4*)((char*)outL + base + off) = L;
}

// x (b, cch, p, n) fp32 -> XT tiles (b, ntile, kt) bf16 hi/lo
__global__ void prep_xt_kernel(const float* __restrict__ x){
  __shared__ float sm[32][33];
  int b = blockIdx.z, k0 = blockIdx.x*32, n0 = blockIdx.y*32;
  int t = threadIdx.x;
  {
    int kk = t >> 3, n4 = (t & 7) << 2;
    int k = k0 + kk; int p = k >> 8, cch = k & 255;
    float4 v = *(const float4*)&x[((size_t)((b*CC+cch)*4 + p))*NPIX + n0 + n4];
    sm[kk][n4] = v.x; sm[kk][n4+1] = v.y; sm[kk][n4+2] = v.z; sm[kk][n4+3] = v.w;
  }
  __syncthreads();
  {
    int nn = t >> 3, k4 = (t & 7) << 2;
    int n = n0 + nn;
    float a[4];
    #pragma unroll
    for (int i=0;i<4;i++) a[i] = sm[k4+i][nn];
    __nv_bfloat16 hh[4];
    #pragma unroll
    for (int i=0;i<4;i++) hh[i] = __float2bfloat16(a[i]);
    uint2 hp = make_uint2(pkbf2(__bfloat162float(hh[0]), __bfloat162float(hh[1])),
                          pkbf2(__bfloat162float(hh[2]), __bfloat162float(hh[3])));
    uint2 lp = make_uint2(pkbf2(a[0]-__bfloat162float(hh[0]), a[1]-__bfloat162float(hh[1])),
                          pkbf2(a[2]-__bfloat162float(hh[2]), a[3]-__bfloat162float(hh[3])));
    size_t tb = ((size_t)((b*8 + (n>>7))*32 + (k0>>5)))*8192;
    uint32_t off = swz64(n & 127, k4 >> 3) + ((k4 >> 2) & 1)*8;
    *(uint2*)((char*)g_XTH + tb + off) = hp;
    *(uint2*)((char*)g_XTL + tb + off) = lp;
  }
}

// ===========================================================================
// mma.sync GEMM: 256m x 128n per CTA, K=1024, bf16x3, BK=64 bulk-fed.
// MODE 0: A=Weff (M=3072), B=XT; each CTA's m-tile is pure Q, K or V.
//         V -> direct bf16 hi/lo (d,n) tiles; Q/K -> smem transpose ->
//         (n,d) hi/lo tiles (Q folded with qscale*log2e).
// MODE 1: A=Wproj, B=OT -> final output (+bias)
// ===========================================================================
#define GSTG 98304u
#define GEMM_SMEM (1024u + 2u*GSTG)

template<int MODE>
__global__ __launch_bounds__(256, 1) void gemm_mma(const float* __restrict__ bias,
                                                   float* __restrict__ outp){
  extern __shared__ char smem[];
  const uint32_t sb = smem_u32(smem);
  const int tid = threadIdx.x;
  const int wid = tid >> 5, lane = tid & 31;
  const int mt = blockIdx.x;
  const int b  = blockIdx.y >> 3;
  const int nt = blockIdx.y & 7;
  const int m0 = mt*256, n0 = nt*128;
  const int wm = (wid >> 1) * 64;
  const int wn = (wid & 1) * 64;

  const char* Ahb = (const char*)(MODE==0 ? g_WeffH : g_WprojH) + (size_t)mt*32*16384;
  const char* Alb = (const char*)(MODE==0 ? g_WeffL : g_WprojL) + (size_t)mt*32*16384;
  const char* Bhb = (const char*)(MODE==0 ? g_XTH : g_OTH) + (size_t)((b*8+nt)*32)*8192;
  const char* Blb = (const char*)(MODE==0 ? g_XTL : g_OTL) + (size_t)((b*8+nt)*32)*8192;

  if (tid == 0){ MBARRIER_INIT(sb+8, 1); MBARRIER_INIT(sb+16, 1); }
  __syncthreads();

  float acc[4][8][4];
  #pragma unroll
  for (int i=0;i<4;i++)
    #pragma unroll
    for (int j=0;j<8;j++)
      #pragma unroll
      for (int r=0;r<4;r++) acc[i][j][r] = 0.f;

  auto issue = [&](int kt2){
    if (tid == 0){
      int buf = kt2 & 1;
      uint32_t mb = sb + 8 + buf*8;
      MBARRIER_EXPECT_TX(mb, GSTG);
      uint32_t d = sb + 1024 + buf*GSTG;
      BULKCP(d,         Ahb + (size_t)kt2*32768, 32768, mb);
      BULKCP(d+32768,   Alb + (size_t)kt2*32768, 32768, mb);
      BULKCP(d+65536,   Bhb + (size_t)kt2*16384, 16384, mb);
      BULKCP(d+81920,   Blb + (size_t)kt2*16384, 16384, mb);
    }
  };

  issue(0);
  for (int kt2 = 0; kt2 < 16; kt2++){
    if (kt2 + 1 < 16) issue(kt2+1);
    MBARRIER_WAIT_PARITY(sb + 8 + (kt2&1)*8, (kt2>>1)&1);
    const uint32_t st = sb + 1024 + (kt2&1)*GSTG;

    #pragma unroll
    for (int s = 0; s < 2; s++){
      const uint32_t Ah = st + s*16384;
      const uint32_t Al = st + 32768 + s*16384;
      const uint32_t Bh = st + 65536 + s*8192;
      const uint32_t Bl = st + 81920 + s*8192;
      #pragma unroll
      for (int ks = 0; ks < 2; ks++){
        uint32_t ah[4][4], al[4][4], bh[8][2], bl[8][2];
        #pragma unroll
        for (int mi = 0; mi < 4; mi++){
          uint32_t row = wm + mi*16 + (lane & 15);
          uint32_t c16 = ks*2 + (lane >> 4);
          uint32_t addr = Ah + swz64(row, c16);
          ldm4(ah[mi], addr);
          ldm4(al[mi], addr + 32768);  // Al = Ah + 32768 for same s
        }
        #pragma unroll
        for (int np = 0; np < 4; np++){
          uint32_t row = wn + np*16 + (lane >> 4)*8 + (lane & 7);
          uint32_t c16 = ks*2 + ((lane >> 3) & 1);
          uint32_t addr = Bh + swz64(row, c16);
          uint32_t r[4];
          ldm4(r, addr);
          bh[np*2][0]=r[0]; bh[np*2][1]=r[1]; bh[np*2+1][0]=r[2]; bh[np*2+1][1]=r[3];
          ldm4(r, addr + 16384);       // Bl = Bh + 16384 for same s
          bl[np*2][0]=r[0]; bl[np*2][1]=r[1]; bl[np*2+1][0]=r[2]; bl[np*2+1][1]=r[3];
        }
        #pragma unroll
        for (int mi=0;mi<4;mi++)
          #pragma unroll
          for (int ni=0;ni<8;ni++) mma16816(acc[mi][ni], ah[mi], bh[ni]);
        #pragma unroll
        for (int mi=0;mi<4;mi++)
          #pragma unroll
          for (int ni=0;ni<8;ni++) mma16816(acc[mi][ni], ah[mi], bl[ni]);
        #pragma unroll
        for (int mi=0;mi<4;mi++)
          #pragma unroll
          for (int ni=0;ni<8;ni++) mma16816(acc[mi][ni], al[mi], bh[ni]);
      }
    }
    __syncthreads();
  }

  if (MODE == 1){
    // final output: out[(b, cch, qc, n)] = acc + bias
    #pragma unroll
    for (int mi=0;mi<4;mi++)
      #pragma unroll
      for (int half=0; half<2; half++){
        int gm = m0 + wm + mi*16 + (lane >> 2) + half*8;
        float bi = bias[gm];
        int qc = gm >> 8; int cch = gm & 255;
        float* dst = outp + ((size_t)((b*CC + cch)*4 + qc))*NPIX;
        #pragma unroll
        for (int ni=0;ni<8;ni++){
          int nn = n0 + wn + ni*8 + (lane & 3)*2;
          float2 v = make_float2(acc[mi][ni][half*2+0] + bi,
                                 acc[mi][ni][half*2+1] + bi);
          *(float2*)&dst[nn] = v;
        }
      }
    return;
  }

  // ---- MODE 0 epilogue: region = Q(0) / K(1) / V(2) ----
  const int region = mt % 3;
  const int qc = mt / 3;
  if (region == 2){
    // V: direct hi/lo stores into (d, n) tiles
    #pragma unroll
    for (int mi=0;mi<4;mi++)
      #pragma unroll
      for (int half=0; half<2; half++){
        int gm = m0 + wm + mi*16 + (lane >> 2) + half*8;
        float bi = bias[gm];
        int o = gm - qc*768; int cch = o & 255;
        int ch = (qc << 8) | cch; int hh = ch >> 7; int dd = ch & 127;
        size_t bhbase = ((size_t)(b*HEADS + hh))*16*16384;
        #pragma unroll
        for (int ni=0;ni<8;ni++){
          int nn = n0 + wn + ni*8 + (lane & 3)*2;
          float v0 = acc[mi][ni][half*2+0] + bi;
          float v1 = acc[mi][ni][half*2+1] + bi;
          __nv_bfloat16 h0 = __float2bfloat16(v0), h1 = __float2bfloat16(v1);
          size_t tb = bhbase + (size_t)(nn>>6)*16384;
          uint32_t off = swz128(dd, (nn&63)>>3) + (nn&7)*2;
          *(uint32_t*)((char*)g_VH + tb + off) =
              pkbf2(__bfloat162float(h0), __bfloat162float(h1));
          *(uint32_t*)((char*)g_VL + tb + off) =
              pkbf2(v0-__bfloat162float(h0), v1-__bfloat162float(h1));
        }
      }
  } else {
    // Q/K: stage fp32 into smem (scale folded), transpose, emit (n,d) tiles
    float* T = (float*)(smem + 1024);   // 256 x 132 fp32 = 135168 B
    const float scl = (region == 0) ? 0.12751875542484462f  // qscale*log2e
                                    : 1.f;
    #pragma unroll
    for (int mi=0;mi<4;mi++)
      #pragma unroll
      for (int half=0; half<2; half++){
        int gm = m0 + wm + mi*16 + (lane >> 2) + half*8;
        int row = gm - m0;
        float bi = bias[gm];
        #pragma unroll
        for (int ni=0;ni<8;ni++){
          int nn = wn + ni*8 + (lane & 3)*2;
          T[row*132 + nn]     = (acc[mi][ni][half*2+0] + bi)*scl;
          T[row*132 + nn + 1] = (acc[mi][ni][half*2+1] + bi)*scl;
        }
      }
    __syncthreads();

    char* dh = (region == 0) ? (char*)g_QTH : (char*)g_KTH;
    char* dl = (region == 0) ? (char*)g_QTL : (char*)g_KTL;
    const int hp = tid >> 7;            // head parity within tile
    const int nl = tid & 127;
    const int n = n0 + nl;
    const int head = qc*2 + hp;
    const size_t tb = ((size_t)((b*HEADS + head)*16 + (n>>6)))*16384;
    const uint32_t r6 = n & 63;
    #pragma unroll
    for (int c16 = 0; c16 < 16; c16++){
      float a[8]; __nv_bfloat16 h[8]; float hf[8];
      #pragma unroll
      for (int i=0;i<8;i++) a[i] = T[(hp*128 + c16*8 + i)*132 + nl];
      #pragma unroll
      for (int i=0;i<8;i++){ h[i] = __float2bfloat16(a[i]); hf[i] = __bfloat162float(h[i]); }
      uint4 H, L;
      H.x = pkbf2(hf[0],hf[1]); H.y = pkbf2(hf[2],hf[3]);
      H.z = pkbf2(hf[4],hf[5]); H.w = pkbf2(hf[6],hf[7]);
      L.x = pkbf2(a[0]-hf[0], a[1]-hf[1]);
      L.y = pkbf2(a[2]-hf[2], a[3]-hf[3]);
      L.z = pkbf2(a[4]-hf[4], a[5]-hf[5]);
      L.w = pkbf2(a[6]-hf[6], a[7]-hf[7]);
      uint32_t off = swz256(r6, c16);
      *(uint4*)(dh + tb + off) = H;
      *(uint4*)(dl + tb + off) = L;
    }
  }
}

// ===========================================================================
// Flash attention, mma.sync bf16x3, bulk-copy fed.
// CTA = (b,h) x 128 queries, 256 thr, 8 warps x 16 q-rows.
// ===========================================================================
#define ASTG 65536u
#define AT_SMEM (1024u + 2u*ASTG)

__global__ __launch_bounds__(256, 1) void attn_mma(){
  extern __shared__ char smem[];
  const uint32_t sb = smem_u32(smem);
  const int tid = threadIdx.x;
  const int wid = tid >> 5, lane = tid & 31;
  const int bh = blockIdx.y;
  const int qi = blockIdx.x;           // q block of 128
  const int q0 = qi * 128;
  const int b = bh >> 3, h = bh & 7;

  if (tid == 0){
    MBARRIER_INIT(sb+8, 1); MBARRIER_INIT(sb+16, 1); MBARRIER_INIT(sb+24, 1);
  }
  __syncthreads();

  // ---- Q load: 2 tiles hi + 2 tiles lo = 64KB into stage0 region
  if (tid == 0){
    MBARRIER_EXPECT_TX(sb+24, 65536);
    const char* qh_g = (const char*)g_QTH + ((size_t)bh*16 + qi*2)*16384;
    const char* ql_g = (const char*)g_QTL + ((size_t)bh*16 + qi*2)*16384;
    BULKCP(sb+1024,         qh_g, 32768, sb+24);
    BULKCP(sb+1024+32768,   ql_g, 32768, sb+24);
  }
  MBARRIER_WAIT_PARITY(sb+24, 0);

  uint32_t qfh[8][4], qfl[8][4];
  {
    uint32_t row = wid*16 + (lane & 15);
    uint32_t base = sb + 1024 + (row >> 6)*16384;
    uint32_t r6 = row & 63;
    #pragma unroll
    for (int kf = 0; kf < 8; kf++){
      uint32_t c16 = kf*2 + (lane >> 4);
      uint32_t addr = base + swz256(r6, c16);
      ldm4(qfh[kf], addr);
      ldm4(qfl[kf], addr + 32768);
    }
  }
  __syncthreads();   // Q consumed; stage0 reusable

  const char* kh_g = (const char*)g_KTH + (size_t)bh*16*16384;
  const char* kl_g = (const char*)g_KTL + (size_t)bh*16*16384;
  const char* vh_g = (const char*)g_VH  + (size_t)bh*16*16384;
  const char* vl_g = (const char*)g_VL  + (size_t)bh*16*16384;

  auto issueKV = [&](int kb){
    if (tid == 0){
      int buf = kb & 1;
      uint32_t mb = sb + 8 + buf*8;
      MBARRIER_EXPECT_TX(mb, ASTG);
      uint32_t d = sb + 1024 + buf*ASTG;
      BULKCP(d,         kh_g + (size_t)kb*16384, 16384, mb);
      BULKCP(d+16384,   kl_g + (size_t)kb*16384, 16384, mb);
      BULKCP(d+32768,   vh_g + (size_t)kb*16384, 16384, mb);
      BULKCP(d+49152,   vl_g + (size_t)kb*16384, 16384, mb);
    }
  };

  float accO[16][4];
  #pragma unroll
  for (int i=0;i<16;i++)
    #pragma unroll
    for (int r=0;r<4;r++) accO[i][r] = 0.f;
  float m0r = -1e30f, m1r = -1e30f, l0 = 0.f, l1 = 0.f;

  issueKV(0);
  for (int kb = 0; kb < 16; kb++){
    if (kb + 1 < 16) issueKV(kb+1);
    MBARRIER_WAIT_PARITY(sb + 8 + (kb&1)*8, (kb>>1)&1);
    const uint32_t st = sb + 1024 + (kb&1)*ASTG;

    // ---- S = Q K^T  (16q x 64k per warp), bf16x3
    float S[8][4];
    #pragma unroll
    for (int i=0;i<8;i++)
      #pragma unroll
      for (int r=0;r<4;r++) S[i][r] = 0.f;
    #pragma unroll
    for (int kf = 0; kf < 8; kf++){
      #pragma unroll
      for (int np = 0; np < 4; np++){
        uint32_t row = np*16 + (lane >> 4)*8 + (lane & 7);
        uint32_t c16 = kf*2 + ((lane >> 3) & 1);
        uint32_t addr = st + swz256(row, c16);
        uint32_t r[4];
        ldm4(r, addr);
        uint32_t b0[2] = {r[0], r[1]}, b1[2] = {r[2], r[3]};
        mma16816(S[np*2],   qfh[kf], b0);
        mma16816(S[np*2+1], qfh[kf], b1);
        mma16816(S[np*2],   qfl[kf], b0);
        mma16816(S[np*2+1], qfl[kf], b1);
        ldm4(r, addr + 16384);
        uint32_t c0[2] = {r[0], r[1]}, c1[2] = {r[2], r[3]};
        mma16816(S[np*2],   qfh[kf], c0);
        mma16816(S[np*2+1], qfh[kf], c1);
      }
    }

    // ---- online softmax (log2 domain; log2e folded into Q)
    float mx0 = -1e30f, mx1 = -1e30f;
    #pragma unroll
    for (int i=0;i<8;i++){
      mx0 = fmaxf(mx0, fmaxf(S[i][0], S[i][1]));
      mx1 = fmaxf(mx1, fmaxf(S[i][2], S[i][3]));
    }
    mx0 = fmaxf(mx0, __shfl_xor_sync(0xffffffffu, mx0, 1));
    mx0 = fmaxf(mx0, __shfl_xor_sync(0xffffffffu, mx0, 2));
    mx1 = fmaxf(mx1, __shfl_xor_sync(0xffffffffu, mx1, 1));
    mx1 = fmaxf(mx1, __shfl_xor_sync(0xffffffffu, mx1, 2));
    float mn0 = fmaxf(m0r, mx0), mn1 = fmaxf(m1r, mx1);
    float al0 = exp2f(m0r - mn0), al1 = exp2f(m1r - mn1);
    m0r = mn0; m1r = mn1;

    float rs0 = 0.f, rs1 = 0.f;
    uint32_t ph[4][4], pl[4][4];
    #pragma unroll
    for (int nf = 0; nf < 8; nf++){
      float p0 = exp2f(S[nf][0] - mn0);
      float p1 = exp2f(S[nf][1] - mn0);
      float p2 = exp2f(S[nf][2] - mn1);
      float p3 = exp2f(S[nf][3] - mn1);
      rs0 += p0 + p1; rs1 += p2 + p3;
      __nv_bfloat16 h0 = __float2bfloat16(p0), h1 = __float2bfloat16(p1);
      __nv_bfloat16 h2 = __float2bfloat16(p2), h3 = __float2bfloat16(p3);
      int kf = nf >> 1, pc = (nf & 1)*2;
      ph[kf][pc+0] = pkbf2(__bfloat162float(h0), __bfloat162float(h1));
      ph[kf][pc+1] = pkbf2(__bfloat162float(h2), __bfloat162float(h3));
      pl[kf][pc+0] = pkbf2(p0-__bfloat162float(h0), p1-__bfloat162float(h1));
      pl[kf][pc+1] = pkbf2(p2-__bfloat162float(h2), p3-__bfloat162float(h3));
    }
    rs0 += __shfl_xor_sync(0xffffffffu, rs0, 1);
    rs0 += __shfl_xor_sync(0xffffffffu, rs0, 2);
    rs1 += __shfl_xor_sync(0xffffffffu, rs1, 1);
    rs1 += __shfl_xor_sync(0xffffffffu, rs1, 2);
    l0 = l0*al0 + rs0; l1 = l1*al1 + rs1;

    #pragma unroll
    for (int i=0;i<16;i++){
      accO[i][0] *= al0; accO[i][1] *= al0;
      accO[i][2] *= al1; accO[i][3] *= al1;
    }

    // ---- accO += P V  (16q x 128d per warp), bf16x3
    const uint32_t vb = st + 32768;
    #pragma unroll
    for (int kf = 0; kf < 4; kf++){
      #pragma unroll
      for (int np = 0; np < 8; np++){
        uint32_t row = np*16 + (lane >> 4)*8 + (lane & 7);
        uint32_t c16 = kf*2 + ((lane >> 3) & 1);
        uint32_t addr = vb + swz128(row, c16);
        uint32_t r[4];
        ldm4(r, addr);
        uint32_t b0[2] = {r[0], r[1]}, b1[2] = {r[2], r[3]};
        mma16816(accO[np*2],   ph[kf], b0);
        mma16816(accO[np*2+1], ph[kf], b1);
        mma16816(accO[np*2],   pl[kf], b0);
        mma16816(accO[np*2+1], pl[kf], b1);
        ldm4(r, addr + 16384);
        uint32_t c0[2] = {r[0], r[1]}, c1[2] = {r[2], r[3]};
        mma16816(accO[np*2],   ph[kf], c0);
        mma16816(accO[np*2+1], ph[kf], c1);
      }
    }
    __syncthreads();
  }

  // ---- epilogue: O/l -> bf16 hi/lo into tiled OT
  float inv0 = 1.f / l0, inv1 = 1.f / l1;
  int na = q0 + wid*16 + (lane >> 2);
  int nb2 = na + 8;
  #pragma unroll
  for (int nf = 0; nf < 16; nf++){
    int ch = h*HD + nf*8 + (lane & 3)*2;
    float v0 = accO[nf][0]*inv0, v1 = accO[nf][1]*inv0;
    float v2 = accO[nf][2]*inv1, v3 = accO[nf][3]*inv1;
    __nv_bfloat16 h0 = __float2bfloat16(v0), h1 = __float2bfloat16(v1);
    __nv_bfloat16 h2 = __float2bfloat16(v2), h3 = __float2bfloat16(v3);
    size_t tba = ((size_t)((b*8 + (na>>7))*32 + (ch>>5)))*8192;
    size_t tbb = ((size_t)((b*8 + (nb2>>7))*32 + (ch>>5)))*8192;
    uint32_t ofa = swz64(na & 127, (ch>>3)&3) + (ch&7)*2;
    uint32_t ofb = swz64(nb2 & 127, (ch>>3)&3) + (ch&7)*2;
    *(uint32_t*)((char*)g_OTH + tba + ofa) = pkbf2(__bfloat162float(h0), __bfloat162float(h1));
    *(uint32_t*)((char*)g_OTL + tba + ofa) = pkbf2(v0-__bfloat162float(h0), v1-__bfloat162float(h1));
    *(uint32_t*)((char*)g_OTH + tbb + ofb) = pkbf2(__bfloat162float(h2), __bfloat162float(h3));
    *(uint32_t*)((char*)g_OTL + tbb + ofb) = pkbf2(v2-__bfloat162float(h2), v3-__bfloat162float(h3));
  }
}

// ---------------------------------------------------------------------------
// Quaternion depthwise 3x3, accumulates into final output.
// ---------------------------------------------------------------------------
__global__ __launch_bounds__(256) void qdwconv_kernel(const float* __restrict__ x,
                                                      const float* __restrict__ w_pe,
                                                      const float* __restrict__ b_pe,
                                                      float* __restrict__ outp){
  __shared__ float xs[4][1024];
  __shared__ float wt[4][4][9];
  const int bid = blockIdx.x;
  const int c = bid & 255, b = bid >> 8;
  const int tid = threadIdx.x;

  #pragma unroll
  for (int p=0;p<4;p++){
    const float* xp = x + ((size_t)((b*CC + c)*4 + p))*NPIX;
    for (int k=tid; k<1024; k+=256) xs[p][k] = xp[k];
  }
  if (tid < 144){
    int qc = tid/36, p = (tid/9)&3, t = tid%9;
    wt[qc][p][t] = c_SGN[qc*4+p] * w_pe[(c_IDX[qc*4+p]*CC + c)*9 + t];
  }
  __syncthreads();

  float bia[4];
  #pragma unroll
  for (int qc=0;qc<4;qc++) bia[qc] = b_pe[qc*CC + c];

  for (int k=tid; k<1024; k+=256){
    int hh = k >> 5, ww = k & 31;
    float acc[4] = {bia[0],bia[1],bia[2],bia[3]};
    #pragma unroll
    for (int p=0;p<4;p++){
      #pragma unroll
      for (int kh=0;kh<3;kh++){
        int h2 = hh + kh - 1;
        if (h2 < 0 || h2 > 31) continue;
        #pragma unroll
        for (int kw=0;kw<3;kw++){
          int w2 = ww + kw - 1;
          if (w2 < 0 || w2 > 31) continue;
          float xv = xs[p][h2*32 + w2];
          #pragma unroll
          for (int qc=0;qc<4;qc++) acc[qc] = fmaf(wt[qc][p][kh*3+kw], xv, acc[qc]);
        }
      }
    }
    #pragma unroll
    for (int qc=0;qc<4;qc++)
      outp[((size_t)((b*CC + c)*4 + qc))*NPIX + k] += acc[qc];
  }
}

// ---------------------------------------------------------------------------
extern "C" void kernel_launch(void* const* d_in, const int* in_sizes, int n_in,
                              void* d_out, int out_size){
  const float* x      = (const float*)d_in[0];
  const float* w_qkv  = (const float*)d_in[1];
  const float* b_qkv  = (const float*)d_in[2];
  const float* w_proj = (const float*)d_in[3];
  const float* b_proj = (const float*)d_in[4];
  const float* w_pe   = (const float*)d_in[5];
  const float* b_pe   = (const float*)d_in[6];
  float* outp = (float*)d_out;

  (void)in_sizes; (void)n_in; (void)out_size;

  cudaFuncSetAttribute(gemm_mma<0>, cudaFuncAttributeMaxDynamicSharedMemorySize,
                       GEMM_SMEM);
  cudaFuncSetAttribute(gemm_mma<1>, cudaFuncAttributeMaxDynamicSharedMemorySize,
                       GEMM_SMEM);
  cudaFuncSetAttribute(attn_mma, cudaFuncAttributeMaxDynamicSharedMemorySize,
                       AT_SMEM);

  // Weight prep (tiled + swizzled, bf16 hi/lo)
  __nv_bfloat16 *weffH, *weffL, *wprojH, *wprojL;
  cudaGetSymbolAddress((void**)&weffH, g_WeffH);
  cudaGetSymbolAddress((void**)&weffL, g_WeffL);
  cudaGetSymbolAddress((void**)&wprojH, g_WprojH);
  cudaGetSymbolAddress((void**)&wprojL, g_WprojL);
  prep_w_kernel<<< MQKV*128/256, 256 >>>(w_qkv, weffH, weffL, 1);
  prep_w_kernel<<< DIM*128/256, 256 >>>(w_proj, wprojH, wprojL, 0);
  prep_xt_kernel<<< dim3(32,32,8), 256 >>>(x);

  // QKV GEMM: emits Q/K (n,d) and V (d,n) bf16 hi/lo tiles directly
  gemm_mma<0><<< dim3(12,64), 256, GEMM_SMEM >>>(b_qkv, nullptr);

  // Attention: mma.sync flash, 8 q-tiles x 64 (b,h)
  attn_mma<<< dim3(8,64), 256, AT_SMEM >>>();

  // Proj: (1024 x 8192) mma.sync bf16x3 -> final output (+bias)
  gemm_mma<1><<< dim3(4,64), 256, GEMM_SMEM >>>(b_proj, outp);

  // Positional depthwise conv, accumulate
  qdwconv_kernel<<< NB*CC, 256 >>>(x, w_pe, b_pe, outp);
}